// round 13
// baseline (speedup 1.0000x reference)
#include <cuda_runtime.h>
#include <cuda_bf16.h>
#include <cuda_fp16.h>
#include <math.h>
#include <stdint.h>

typedef __nv_bfloat16 bf16;

#define BQ 16
#define TQ 512
#define DQ 1024
#define FFQ 2048
#define EQ 4
#define CLSQ 1200
#define MQ (BQ*TQ)

// GEMM tiling
#define GBM 128
#define GBN 128
#define GBK 32
#define A_LO_OFF 10240
#define B_HI_OFF 20480
#define B_LO_OFF 30720
#define SMEM_GEMM3 (2*40960)   // bf16 3-pass
#define SMEM_GEMM2 (2*30720)   // fp16 2-pass

__device__ float g_h[(size_t)MQ * DQ];
__device__ float g_moe[(size_t)MQ * DQ];
__device__ float g_gates[MQ * EQ];
__device__ float g_probs[MQ * EQ];
__device__ float g_sum[DQ];
__device__ float g_sumsq[DQ];
__device__ float g_scale[DQ];
__device__ float g_shift[DQ];

__device__ int g_selidx[EQ * MQ];
__device__ int g_dilidx[EQ * MQ];
__device__ int g_selcnt[EQ];
__device__ int g_dilcnt[EQ];

__device__ bf16 g_xh[(size_t)MQ * DQ],  g_xl[(size_t)MQ * DQ];
__device__ __half g_hh[(size_t)MQ * DQ],  g_hl[(size_t)MQ * DQ];
__device__ __half g_y1h[(size_t)MQ * FFQ], g_y1l[(size_t)MQ * FFQ];
__device__ bf16 g_fh[(size_t)MQ * DQ],  g_fl[(size_t)MQ * DQ];
__device__ __half g_w1[(size_t)EQ * FFQ * 3 * DQ];
__device__ __half g_w2[(size_t)EQ * DQ * 3 * FFQ];
__device__ bf16 g_fc1h[DQ * DQ], g_fc1l[DQ * DQ];
__device__ bf16 g_owh[CLSQ * DQ], g_owl[CLSQ * DQ];

__device__ __forceinline__ uint32_t smem_u32(const void* p) {
    uint32_t a;
    asm("{ .reg .u64 t; cvta.to.shared.u64 t, %1; cvt.u32.u64 %0, t; }" : "=r"(a) : "l"(p));
    return a;
}
__device__ __forceinline__ void cp16(uint32_t dst, const void* src, int pred) {
    int sz = pred ? 16 : 0;
    asm volatile("cp.async.cg.shared.global [%0], [%1], 16, %2;"
                 :: "r"(dst), "l"(src), "r"(sz));
}
__device__ __forceinline__ void ldsm4(uint32_t* r, uint32_t addr) {
    asm volatile("ldmatrix.sync.aligned.m8n8.x4.shared.b16 {%0,%1,%2,%3}, [%4];"
                 : "=r"(r[0]), "=r"(r[1]), "=r"(r[2]), "=r"(r[3]) : "r"(addr));
}
__device__ __forceinline__ void mma_bf16(float* d, const uint32_t* a, const uint32_t* b) {
    asm volatile(
        "mma.sync.aligned.m16n8k16.row.col.f32.bf16.bf16.f32 "
        "{%0,%1,%2,%3}, {%4,%5,%6,%7}, {%8,%9}, {%0,%1,%2,%3};"
        : "+f"(d[0]), "+f"(d[1]), "+f"(d[2]), "+f"(d[3])
        : "r"(a[0]), "r"(a[1]), "r"(a[2]), "r"(a[3]), "r"(b[0]), "r"(b[1]));
}
__device__ __forceinline__ void mma_f16(float* d, const uint32_t* a, const uint32_t* b) {
    asm volatile(
        "mma.sync.aligned.m16n8k16.row.col.f32.f16.f16.f32 "
        "{%0,%1,%2,%3}, {%4,%5,%6,%7}, {%8,%9}, {%0,%1,%2,%3};"
        : "+f"(d[0]), "+f"(d[1]), "+f"(d[2]), "+f"(d[3])
        : "r"(a[0]), "r"(a[1]), "r"(a[2]), "r"(a[3]), "r"(b[0]), "r"(b[1]));
}
__device__ __forceinline__ uint32_t pk2(bf16 a, bf16 b) {
    __nv_bfloat162 t = __halves2bfloat162(a, b);
    return *reinterpret_cast<uint32_t*>(&t);
}
__device__ __forceinline__ uint32_t pk2h(__half a, __half b) {
    __half2 t = __halves2half2(a, b);
    return *reinterpret_cast<uint32_t*>(&t);
}

// C[m,c] = sum_{k'} A[m+shift(k'), kcol] * W[c,k']
// H2=0: bf16 3-pass (A hi/lo x B hi/lo, drop lo*lo).  H2=1: fp16 2-pass (A hi/lo x B single).
// USE_IDX: tile rows gathered through idxlist (count at *cntptr); padding predicated.
// EPI 0: Cf = acc+bias (guard c<Nrows)
// EPI 1: relu(acc+bias) -> Coh/Col (fp16 hi/lo), rows scattered by idx
// EPI 2: (acc+bias)*gate[m,ecur] (+Cf if accum) -> Cf, rows scattered by idx
template<int EPI, int USE_IDX, int H2>
__global__ __launch_bounds__(256, 1)
void gemm_hmma(const uint16_t* __restrict__ Ah, const uint16_t* __restrict__ Al,
               const uint16_t* __restrict__ Bh, const uint16_t* __restrict__ Bl,
               const float* __restrict__ bias,
               float* __restrict__ Cf, __half* __restrict__ Coh, __half* __restrict__ Col,
               const float* __restrict__ gates, int ecur, int accum,
               const int* __restrict__ idxlist, const int* __restrict__ cntptr,
               int Nrows, int Kseg, int KW, int strideA)
{
    constexpr int STAGE = H2 ? 30720 : 40960;
    extern __shared__ char smem[];
    __shared__ int sidx[GBM];
    const int tid = threadIdx.x;
    const int lane = tid & 31;
    const int wid = tid >> 5;
    const int wr = wid >> 2;      // 0..1 (m)
    const int wc = wid & 3;       // 0..3 (n)
    const int m0 = blockIdx.y * GBM;
    const int c0 = blockIdx.x * GBN;
    const int K = Kseg * KW;
    const int KT = K >> 5;
    const int HALO = KW >> 1;
    const uint32_t sb = smem_u32(smem);

    if (USE_IDX) {
        int cnt = cntptr[0];
        if (m0 >= cnt) return;
        if (tid < GBM) {
            int gi = m0 + tid;
            sidx[tid] = (gi < cnt) ? idxlist[gi] : -1;
        }
        __syncthreads();
    }

    float acc[4][4][4];
    #pragma unroll
    for (int i = 0; i < 4; i++)
        #pragma unroll
        for (int j = 0; j < 4; j++)
            #pragma unroll
            for (int k = 0; k < 4; k++) acc[i][j][k] = 0.f;

    auto load_stage = [&](int stage, int kt) {
        const int k0 = kt * GBK;
        const int kw = k0 / Kseg;
        const int kcol = k0 - kw * Kseg;
        const int dt = kw - HALO;
        const uint32_t ss = sb + stage * STAGE;
        #pragma unroll
        for (int i = 0; i < 2; i++) {
            int idx = i * 256 + tid;
            int r = idx >> 2, c = idx & 3;
            int m, valid;
            if (USE_IDX) { m = sidx[r]; valid = (m >= 0); }
            else { m = m0 + r; valid = 1; }
            int t = (m & (TQ - 1)) + dt;
            int pr = valid && (t >= 0) && (t < TQ);
            int msafe = pr ? (m + dt) : 0;
            size_t off = (size_t)msafe * strideA + kcol + c * 8;
            uint32_t d = ss + r * 80 + c * 16;
            cp16(d, Ah + off, pr);
            cp16(d + A_LO_OFF, Al + off, pr);
        }
        #pragma unroll
        for (int i = 0; i < 2; i++) {
            int idx = i * 256 + tid;
            int r = idx >> 2, c = idx & 3;
            int n = c0 + r;
            int pr = n < Nrows;
            size_t off = pr ? ((size_t)n * K + k0 + c * 8) : 0;
            uint32_t d = ss + B_HI_OFF + r * 80 + c * 16;
            cp16(d, Bh + off, pr);
            if (!H2) cp16(d + (B_LO_OFF - B_HI_OFF), Bl + off, pr);
        }
        asm volatile("cp.async.commit_group;" ::: "memory");
    };

    load_stage(0, 0);

    const int arow = wr * 64 + (lane & 15);            // + mi*16
    const uint32_t achunk = (lane & 16) ? 16u : 0u;    // + ks*32
    const int brow = wc * 32 + (lane & 7) + ((lane & 16) ? 8 : 0);  // + nb*16
    const uint32_t bchunk = (lane & 8) ? 16u : 0u;

    for (int kt = 0; kt < KT; kt++) {
        const uint32_t cs = sb + (kt & 1) * STAGE;
        asm volatile("cp.async.wait_group 0;" ::: "memory");
        __syncthreads();
        if (kt + 1 < KT) load_stage((kt + 1) & 1, kt + 1);

        #pragma unroll
        for (int ks = 0; ks < 2; ks++) {
            uint32_t ah[4][4], al[4][4], bh[4][2], bl[4][2];
            #pragma unroll
            for (int mi = 0; mi < 4; mi++) {
                uint32_t ad = cs + (arow + mi * 16) * 80 + ks * 32 + achunk;
                ldsm4(ah[mi], ad);
                ldsm4(al[mi], ad + A_LO_OFF);
            }
            #pragma unroll
            for (int nb = 0; nb < 2; nb++) {
                uint32_t tmp[4];
                uint32_t bd = cs + B_HI_OFF + (brow + nb * 16) * 80 + ks * 32 + bchunk;
                ldsm4(tmp, bd);
                bh[nb * 2][0] = tmp[0]; bh[nb * 2][1] = tmp[1];
                bh[nb * 2 + 1][0] = tmp[2]; bh[nb * 2 + 1][1] = tmp[3];
                if (!H2) {
                    ldsm4(tmp, bd + (B_LO_OFF - B_HI_OFF));
                    bl[nb * 2][0] = tmp[0]; bl[nb * 2][1] = tmp[1];
                    bl[nb * 2 + 1][0] = tmp[2]; bl[nb * 2 + 1][1] = tmp[3];
                }
            }
            #pragma unroll
            for (int mi = 0; mi < 4; mi++)
                #pragma unroll
                for (int ni = 0; ni < 4; ni++) {
                    if (H2) {
                        mma_f16(acc[mi][ni], ah[mi], bh[ni]);
                        mma_f16(acc[mi][ni], al[mi], bh[ni]);
                    } else {
                        mma_bf16(acc[mi][ni], ah[mi], bh[ni]);
                        mma_bf16(acc[mi][ni], ah[mi], bl[ni]);
                        mma_bf16(acc[mi][ni], al[mi], bh[ni]);
                    }
                }
        }
        __syncthreads();
    }

    // epilogue: direct register -> gmem (rows via idx when USE_IDX)
    #pragma unroll
    for (int mi = 0; mi < 4; mi++) {
        int lr0 = wr * 64 + mi * 16 + (lane >> 2);
        int lr1 = lr0 + 8;
        int r0, r1, v0, v1;
        if (USE_IDX) {
            r0 = sidx[lr0]; r1 = sidx[lr1];
            v0 = (r0 >= 0); v1 = (r1 >= 0);
            if (r0 < 0) r0 = 0;
            if (r1 < 0) r1 = 0;
        } else {
            r0 = m0 + lr0; r1 = m0 + lr1; v0 = 1; v1 = 1;
        }
        float gg0 = 0.f, gg1 = 0.f;
        if (EPI == 2) {
            if (v0) gg0 = gates[r0 * EQ + ecur];
            if (v1) gg1 = gates[r1 * EQ + ecur];
        }
        #pragma unroll
        for (int ni = 0; ni < 4; ni++) {
            int c = c0 + wc * 32 + ni * 8 + (lane & 3) * 2;
            if (c >= Nrows) continue;
            float2 bv = *reinterpret_cast<const float2*>(bias + c);
            float* a = acc[mi][ni];
            float w0 = a[0] + bv.x, w1 = a[1] + bv.y;
            float w2 = a[2] + bv.x, w3 = a[3] + bv.y;
            if (EPI == 0) {
                if (v0) *reinterpret_cast<float2*>(Cf + (size_t)r0 * Nrows + c) = make_float2(w0, w1);
                if (v1) *reinterpret_cast<float2*>(Cf + (size_t)r1 * Nrows + c) = make_float2(w2, w3);
            } else if (EPI == 1) {
                w0 = fmaxf(w0, 0.f); w1 = fmaxf(w1, 0.f);
                w2 = fmaxf(w2, 0.f); w3 = fmaxf(w3, 0.f);
                __half h0 = __float2half(w0), h1 = __float2half(w1);
                __half h2 = __float2half(w2), h3 = __float2half(w3);
                __half l0 = __float2half(w0 - __half2float(h0));
                __half l1 = __float2half(w1 - __half2float(h1));
                __half l2 = __float2half(w2 - __half2float(h2));
                __half l3 = __float2half(w3 - __half2float(h3));
                if (v0) {
                    *reinterpret_cast<uint32_t*>(Coh + (size_t)r0 * Nrows + c) = pk2h(h0, h1);
                    *reinterpret_cast<uint32_t*>(Col + (size_t)r0 * Nrows + c) = pk2h(l0, l1);
                }
                if (v1) {
                    *reinterpret_cast<uint32_t*>(Coh + (size_t)r1 * Nrows + c) = pk2h(h2, h3);
                    *reinterpret_cast<uint32_t*>(Col + (size_t)r1 * Nrows + c) = pk2h(l2, l3);
                }
            } else {
                w0 *= gg0; w1 *= gg0; w2 *= gg1; w3 *= gg1;
                if (accum) {
                    if (v0) {
                        float2 o0 = *reinterpret_cast<const float2*>(Cf + (size_t)r0 * Nrows + c);
                        w0 += o0.x; w1 += o0.y;
                    }
                    if (v1) {
                        float2 o1 = *reinterpret_cast<const float2*>(Cf + (size_t)r1 * Nrows + c);
                        w2 += o1.x; w3 += o1.y;
                    }
                }
                if (v0) *reinterpret_cast<float2*>(Cf + (size_t)r0 * Nrows + c) = make_float2(w0, w1);
                if (v1) *reinterpret_cast<float2*>(Cf + (size_t)r1 * Nrows + c) = make_float2(w2, w3);
            }
        }
    }
}

__global__ void split_kernel(const float* __restrict__ src, bf16* __restrict__ h,
                             bf16* __restrict__ l, int n) {
    int i = blockIdx.x * 256 + threadIdx.x;
    if (i < n) {
        float v = src[i];
        bf16 hh = __float2bfloat16(v);
        h[i] = hh;
        l[i] = __float2bfloat16(v - __bfloat162float(hh));
    }
}
// [rows][Kseg][KW] -> [rows][KW][Kseg], single fp16
__global__ void perm_half(const float* __restrict__ w, __half* __restrict__ o,
                          int rows, int Kseg) {
    int i = blockIdx.x * 256 + threadIdx.x;
    if (i >= rows * 3 * Kseg) return;
    int row = i / (3 * Kseg);
    int rem = i - row * 3 * Kseg;
    int kw = rem / Kseg, d = rem - kw * Kseg;
    o[i] = __float2half(w[(size_t)row * 3 * Kseg + (size_t)d * 3 + kw]);
}

__global__ void zero_moe() {
    size_t i = (size_t)blockIdx.x * 256 + threadIdx.x;
    reinterpret_cast<float4*>(g_moe)[i] = make_float4(0.f, 0.f, 0.f, 0.f);
}

// per-expert sorted index lists: selected (gate>0) and dilated (neighbor window)
__global__ void build_idx() {
    int e = blockIdx.x;
    int tid = threadIdx.x;   // 256
    __shared__ int ss[256], sd[256];
    int base = tid * 32;
    uint32_t selm = 0, dilm = 0;
    for (int i = 0; i < 32; i++) {
        int n = base + i;
        int t = n & (TQ - 1);
        bool sel = g_gates[n * EQ + e] > 0.f;
        bool dil = sel;
        if (t > 0) dil = dil || (g_gates[(n - 1) * EQ + e] > 0.f);
        if (t < TQ - 1) dil = dil || (g_gates[(n + 1) * EQ + e] > 0.f);
        if (sel) selm |= (1u << i);
        if (dil) dilm |= (1u << i);
    }
    int cs = __popc(selm), cd = __popc(dilm);
    ss[tid] = cs; sd[tid] = cd;
    __syncthreads();
    for (int o = 1; o < 256; o <<= 1) {
        int vs = (tid >= o) ? ss[tid - o] : 0;
        int vd = (tid >= o) ? sd[tid - o] : 0;
        __syncthreads();
        ss[tid] += vs; sd[tid] += vd;
        __syncthreads();
    }
    int ps = ss[tid] - cs, pd = sd[tid] - cd;
    for (int i = 0; i < 32; i++) {
        int n = base + i;
        if (selm & (1u << i)) g_selidx[e * MQ + ps++] = n;
        if (dilm & (1u << i)) g_dilidx[e * MQ + pd++] = n;
    }
    if (tid == 255) { g_selcnt[e] = ss[255]; g_dilcnt[e] = sd[255]; }
}

__device__ __forceinline__ float blockReduceSum256(float v, float* sh) {
    int tid = threadIdx.x;
    #pragma unroll
    for (int o = 16; o > 0; o >>= 1) v += __shfl_down_sync(0xffffffffu, v, o);
    if ((tid & 31) == 0) sh[tid >> 5] = v;
    __syncthreads();
    if (tid < 8) {
        float r = sh[tid];
        #pragma unroll
        for (int o = 4; o > 0; o >>= 1) r += __shfl_down_sync(0xffu, r, o);
        if (tid == 0) sh[0] = r;
    }
    __syncthreads();
    float r = sh[0];
    __syncthreads();
    return r;
}
__device__ __forceinline__ float blockReduceMax256(float v, float* sh) {
    int tid = threadIdx.x;
    #pragma unroll
    for (int o = 16; o > 0; o >>= 1) v = fmaxf(v, __shfl_down_sync(0xffffffffu, v, o));
    if ((tid & 31) == 0) sh[tid >> 5] = v;
    __syncthreads();
    if (tid < 8) {
        float r = sh[tid];
        #pragma unroll
        for (int o = 4; o > 0; o >>= 1) r = fmaxf(r, __shfl_down_sync(0xffu, r, o));
        if (tid == 0) sh[0] = r;
    }
    __syncthreads();
    float r = sh[0];
    __syncthreads();
    return r;
}

__global__ void init_kernel() {
    int i = threadIdx.x;
    for (int d = i; d < DQ; d += 256) { g_sum[d] = 0.f; g_sumsq[d] = 0.f; }
}

__global__ void stats_partial(const int* __restrict__ mask) {
    int d = blockIdx.y * 256 + threadIdx.x;
    int r0 = blockIdx.x * 256;
    float s = 0.f, s2 = 0.f;
    for (int r = 0; r < 256; r++) {
        int n = r0 + r;
        if (mask[n]) {
            float v = g_h[(size_t)n * DQ + d];
            s += v; s2 += v * v;
        }
    }
    atomicAdd(&g_sum[d], s);
    atomicAdd(&g_sumsq[d], s2);
}

__global__ void stats_final(const int* __restrict__ mask,
                            const float* __restrict__ bn_g,
                            const float* __restrict__ bn_b) {
    __shared__ float sh[32];
    __shared__ float s_cnt;
    int tid = threadIdx.x;  // 1024
    float c = 0.f;
    for (int n = tid; n < MQ; n += 1024) c += (float)mask[n];
    #pragma unroll
    for (int o = 16; o > 0; o >>= 1) c += __shfl_down_sync(0xffffffffu, c, o);
    if ((tid & 31) == 0) sh[tid >> 5] = c;
    __syncthreads();
    if (tid < 32) {
        c = sh[tid];
        #pragma unroll
        for (int o = 16; o > 0; o >>= 1) c += __shfl_down_sync(0xffffffffu, c, o);
        if (tid == 0) s_cnt = fmaxf(c, 1.f);
    }
    __syncthreads();
    float cnt = s_cnt;
    int d = tid;
    float mean = g_sum[d] / cnt;
    float var = fmaxf(g_sumsq[d] / cnt - mean * mean, 0.f);
    float sc = rsqrtf(var + 1e-5f) * bn_g[d];
    g_scale[d] = sc;
    g_shift[d] = bn_b[d] - mean * sc;
}

__global__ void norm_gate(const int* __restrict__ mask,
                          const float* __restrict__ pe,
                          const float* __restrict__ gate_w) {
    int n = blockIdx.x;
    int t = n % TQ;
    int m = mask[n];
    int tid = threadIdx.x;
    float g0 = 0.f, g1 = 0.f, g2 = 0.f, g3 = 0.f;
    for (int d = tid; d < DQ; d += 256) {
        float v = g_h[(size_t)n * DQ + d];
        if (m) v = v * g_scale[d] + g_shift[d];
        v = fmaxf(v, 0.f) + pe[t * DQ + d];
        __half hh = __float2half(v);
        g_hh[(size_t)n * DQ + d] = hh;
        g_hl[(size_t)n * DQ + d] = __float2half(v - __half2float(hh));
        const float4 gw = *reinterpret_cast<const float4*>(gate_w + d * EQ);
        g0 += v * gw.x; g1 += v * gw.y; g2 += v * gw.z; g3 += v * gw.w;
    }
    __shared__ float sh[8][4];
    #pragma unroll
    for (int o = 16; o > 0; o >>= 1) {
        g0 += __shfl_down_sync(0xffffffffu, g0, o);
        g1 += __shfl_down_sync(0xffffffffu, g1, o);
        g2 += __shfl_down_sync(0xffffffffu, g2, o);
        g3 += __shfl_down_sync(0xffffffffu, g3, o);
    }
    if ((tid & 31) == 0) {
        int w = tid >> 5;
        sh[w][0] = g0; sh[w][1] = g1; sh[w][2] = g2; sh[w][3] = g3;
    }
    __syncthreads();
    if (tid == 0) {
        float l[4] = {0.f, 0.f, 0.f, 0.f};
        for (int w = 0; w < 8; w++)
            for (int e = 0; e < 4; e++) l[e] += sh[w][e];
        float mx = fmaxf(fmaxf(l[0], l[1]), fmaxf(l[2], l[3]));
        float ex[4], s = 0.f;
        for (int e = 0; e < 4; e++) { ex[e] = expf(l[e] - mx); s += ex[e]; }
        for (int e = 0; e < 4; e++) g_probs[n * EQ + e] = ex[e] / s;
        int i0 = 0;
        for (int e = 1; e < 4; e++) if (l[e] > l[i0]) i0 = e;
        int i1 = -1;
        for (int e = 0; e < 4; e++) {
            if (e == i0) continue;
            if (i1 < 0 || l[e] > l[i1]) i1 = e;
        }
        float ee = expf(l[i1] - l[i0]);
        float gt[4] = {0.f, 0.f, 0.f, 0.f};
        gt[i0] = 1.f / (1.f + ee);
        gt[i1] = ee / (1.f + ee);
        for (int e = 0; e < 4; e++) g_gates[n * EQ + e] = gt[e];
    }
}

__global__ void ln_kernel(const float* __restrict__ ln_g,
                          const float* __restrict__ ln_b,
                          float* __restrict__ feat,
                          float* __restrict__ featn) {
    __shared__ float sh[8];
    int n = blockIdx.x;
    int tid = threadIdx.x;
    float v[4];
    float s = 0.f;
    #pragma unroll
    for (int i = 0; i < 4; i++) {
        int d = tid + i * 256;
        v[i] = g_moe[(size_t)n * DQ + d];
        s += v[i];
    }
    float mu = blockReduceSum256(s, sh) * (1.f / DQ);
    float q = 0.f;
    #pragma unroll
    for (int i = 0; i < 4; i++) { float dd = v[i] - mu; q += dd * dd; }
    float var = blockReduceSum256(q, sh) * (1.f / DQ);
    float r = rsqrtf(var + 1e-6f);
    float f[4];
    float ss = 0.f;
    #pragma unroll
    for (int i = 0; i < 4; i++) {
        int d = tid + i * 256;
        f[i] = (v[i] - mu) * r * ln_g[d] + ln_b[d];
        feat[(size_t)n * DQ + d] = f[i];
        bf16 hh = __float2bfloat16(f[i]);
        g_fh[(size_t)n * DQ + d] = hh;
        g_fl[(size_t)n * DQ + d] = __float2bfloat16(f[i] - __bfloat162float(hh));
        ss += f[i] * f[i];
    }
    float nrm = fmaxf(sqrtf(blockReduceSum256(ss, sh)), 1e-12f);
    float inv = 1.f / nrm;
    #pragma unroll
    for (int i = 0; i < 4; i++) {
        int d = tid + i * 256;
        featn[(size_t)n * DQ + d] = f[i] * inv;
    }
}

__global__ void softmax_kernel(const float* __restrict__ logits,
                               float* __restrict__ logp,
                               float* __restrict__ p) {
    __shared__ float sh[8];
    int n = blockIdx.x;
    int tid = threadIdx.x;
    const float* row = logits + (size_t)n * CLSQ;
    float mx = -1e30f;
    for (int c = tid; c < CLSQ; c += 256) mx = fmaxf(mx, row[c]);
    mx = blockReduceMax256(mx, sh);
    float s = 0.f;
    for (int c = tid; c < CLSQ; c += 256) s += expf(row[c] - mx);
    s = blockReduceSum256(s, sh);
    float lse = mx + logf(s);
    for (int c = tid; c < CLSQ; c += 256) {
        float lp = row[c] - lse;
        logp[(size_t)n * CLSQ + c] = lp;
        p[(size_t)n * CLSQ + c] = expf(lp);
    }
}

__global__ void aux_kernel(float* __restrict__ out_aux) {
    __shared__ float sh[8];
    int tid = threadIdx.x;
    float imp[4] = {0.f, 0.f, 0.f, 0.f};
    float frc[4] = {0.f, 0.f, 0.f, 0.f};
    for (int n = tid; n < MQ; n += 256) {
        #pragma unroll
        for (int e = 0; e < 4; e++) {
            imp[e] += g_probs[n * EQ + e];
            frc[e] += (g_gates[n * EQ + e] > 0.f) ? 1.f : 0.f;
        }
    }
    float tot[8];
    #pragma unroll
    for (int e = 0; e < 4; e++) tot[e] = blockReduceSum256(imp[e], sh);
    #pragma unroll
    for (int e = 0; e < 4; e++) tot[4 + e] = blockReduceSum256(frc[e], sh);
    if (tid == 0) {
        float aux = 0.f;
        for (int e = 0; e < 4; e++)
            aux += (tot[4 + e] / (float)MQ) * (tot[e] / (float)MQ);
        out_aux[0] = (float)EQ * aux;
    }
}

extern "C" void kernel_launch(void* const* d_in, const int* in_sizes, int n_in,
                              void* d_out, int out_size) {
    const float* x      = (const float*)d_in[0];
    const int*   mask   = (const int*)  d_in[1];
    const float* fc1_w  = (const float*)d_in[2];
    const float* fc1_b  = (const float*)d_in[3];
    const float* bn_g   = (const float*)d_in[4];
    const float* bn_b   = (const float*)d_in[5];
    const float* pe     = (const float*)d_in[6];
    const float* gate_w = (const float*)d_in[7];
    const float* ew1    = (const float*)d_in[8];
    const float* eb1    = (const float*)d_in[9];
    const float* ew2    = (const float*)d_in[10];
    const float* eb2    = (const float*)d_in[11];
    const float* ln_g   = (const float*)d_in[12];
    const float* ln_b   = (const float*)d_in[13];
    const float* out_w  = (const float*)d_in[14];
    const float* out_b  = (const float*)d_in[15];

    float* out = (float*)d_out;
    const size_t FEAT = (size_t)MQ * DQ;
    const size_t LGT  = (size_t)MQ * CLSQ;
    float* feat   = out;
    float* featn  = out + FEAT;
    float* logits = out + 2 * FEAT;
    float* logp   = logits + LGT;
    float* p      = logp + LGT;
    float* aux    = p + LGT;

    float *h, *moe, *gates;
    bf16 *xh, *xl, *fh, *fl, *fc1h, *fc1l, *owh, *owl;
    __half *hh, *hl, *y1h, *y1l, *w1, *w2;
    int *selidx, *dilidx, *selcnt, *dilcnt;
    cudaGetSymbolAddress((void**)&h,     g_h);
    cudaGetSymbolAddress((void**)&moe,   g_moe);
    cudaGetSymbolAddress((void**)&gates, g_gates);
    cudaGetSymbolAddress((void**)&xh,  g_xh);   cudaGetSymbolAddress((void**)&xl,  g_xl);
    cudaGetSymbolAddress((void**)&hh,  g_hh);   cudaGetSymbolAddress((void**)&hl,  g_hl);
    cudaGetSymbolAddress((void**)&y1h, g_y1h);  cudaGetSymbolAddress((void**)&y1l, g_y1l);
    cudaGetSymbolAddress((void**)&fh,  g_fh);   cudaGetSymbolAddress((void**)&fl,  g_fl);
    cudaGetSymbolAddress((void**)&w1,  g_w1);   cudaGetSymbolAddress((void**)&w2,  g_w2);
    cudaGetSymbolAddress((void**)&fc1h, g_fc1h); cudaGetSymbolAddress((void**)&fc1l, g_fc1l);
    cudaGetSymbolAddress((void**)&owh, g_owh);  cudaGetSymbolAddress((void**)&owl, g_owl);
    cudaGetSymbolAddress((void**)&selidx, g_selidx);
    cudaGetSymbolAddress((void**)&dilidx, g_dilidx);
    cudaGetSymbolAddress((void**)&selcnt, g_selcnt);
    cudaGetSymbolAddress((void**)&dilcnt, g_dilcnt);

    cudaFuncSetAttribute(gemm_hmma<0,0,0>, cudaFuncAttributeMaxDynamicSharedMemorySize, SMEM_GEMM3);
    cudaFuncSetAttribute(gemm_hmma<1,1,1>, cudaFuncAttributeMaxDynamicSharedMemorySize, SMEM_GEMM2);
    cudaFuncSetAttribute(gemm_hmma<2,1,1>, cudaFuncAttributeMaxDynamicSharedMemorySize, SMEM_GEMM2);

    init_kernel<<<1, 256>>>();

    split_kernel<<<(MQ * DQ) / 256, 256>>>(x, xh, xl, MQ * DQ);
    split_kernel<<<(DQ * DQ) / 256, 256>>>(fc1_w, fc1h, fc1l, DQ * DQ);
    split_kernel<<<(CLSQ * DQ) / 256, 256>>>(out_w, owh, owl, CLSQ * DQ);
    perm_half<<<(EQ * FFQ * 3 * DQ) / 256, 256>>>(ew1, w1, EQ * FFQ, DQ);
    perm_half<<<(EQ * DQ * 3 * FFQ) / 256, 256>>>(ew2, w2, EQ * DQ, FFQ);

    // fc1: bf16 3-pass (keeps gating logits high-precision)
    gemm_hmma<0,0,0><<<dim3(DQ / GBN, MQ / GBM), 256, SMEM_GEMM3>>>(
        (const uint16_t*)xh, (const uint16_t*)xl,
        (const uint16_t*)fc1h, (const uint16_t*)fc1l,
        fc1_b, h, nullptr, nullptr, nullptr, 0, 0,
        nullptr, nullptr, DQ, DQ, 1, DQ);

    stats_partial<<<dim3(32, 4), 256>>>(mask);
    stats_final<<<1, 1024>>>(mask, bn_g, bn_b);
    norm_gate<<<MQ, 256>>>(mask, pe, gate_w);
    build_idx<<<EQ, 256>>>();
    zero_moe<<<(MQ * DQ / 4) / 256, 256>>>();

    for (int e = 0; e < EQ; e++) {
        // conv1: fp16 2-pass on dilated token set
        gemm_hmma<1,1,1><<<dim3(FFQ / GBN, MQ / GBM), 256, SMEM_GEMM2>>>(
            (const uint16_t*)hh, (const uint16_t*)hl,
            (const uint16_t*)(w1 + (size_t)e * FFQ * 3 * DQ), nullptr,
            eb1 + e * FFQ, nullptr, y1h, y1l, nullptr, 0, 0,
            dilidx + e * MQ, dilcnt + e, FFQ, DQ, 3, DQ);
        // conv2: fp16 2-pass on selected token set, gate-scaled accumulate
        gemm_hmma<2,1,1><<<dim3(DQ / GBN, MQ / GBM), 256, SMEM_GEMM2>>>(
            (const uint16_t*)y1h, (const uint16_t*)y1l,
            (const uint16_t*)(w2 + (size_t)e * DQ * 3 * FFQ), nullptr,
            eb2 + e * DQ, moe, nullptr, nullptr, gates, e, 1,
            selidx + e * MQ, selcnt + e, DQ, FFQ, 3, FFQ);
    }

    ln_kernel<<<MQ, 256>>>(ln_g, ln_b, feat, featn);

    // classifier: bf16 3-pass (protects logits accuracy)
    gemm_hmma<0,0,0><<<dim3((CLSQ + GBN - 1) / GBN, MQ / GBM), 256, SMEM_GEMM3>>>(
        (const uint16_t*)fh, (const uint16_t*)fl,
        (const uint16_t*)owh, (const uint16_t*)owl,
        out_b, logits, nullptr, nullptr, nullptr, 0, 0,
        nullptr, nullptr, CLSQ, DQ, 1, DQ);

    softmax_kernel<<<MQ, 256>>>(logits, logp, p);
    aux_kernel<<<1, 256>>>(aux);
}

// round 14
// speedup vs baseline: 1.4875x; 1.4875x over previous
#include <cuda_runtime.h>
#include <cuda_bf16.h>
#include <math.h>
#include <stdint.h>

typedef __nv_bfloat16 bf16;

#define BQ 16
#define TQ 512
#define DQ 1024
#define FFQ 2048
#define EQ 4
#define CLSQ 1200
#define MQ (BQ*TQ)

// GEMM tiling
#define GBM 128
#define GBN 128
#define GBK 32
#define A_LO_OFF 10240
#define B_HI_OFF 20480
#define B_LO_OFF 30720
#define STAGE_BYTES 40960
#define SMEM_GEMM (2*STAGE_BYTES)   // 81920

__device__ float g_h[(size_t)MQ * DQ];
__device__ float g_moe2[(size_t)2 * MQ * DQ];   // slot-major: [slot][token][d]
__device__ float g_gates[MQ * EQ];
__device__ float g_probs[MQ * EQ];
__device__ float g_sum[DQ];
__device__ float g_sumsq[DQ];
__device__ float g_scale[DQ];
__device__ float g_shift[DQ];

__device__ int g_selidx[EQ * MQ];   // encoded (n<<1)|slot
__device__ int g_dilidx[EQ * MQ];   // plain n
__device__ int g_selcnt[EQ];
__device__ int g_dilcnt[EQ];

__device__ bf16 g_xh[(size_t)MQ * DQ],  g_xl[(size_t)MQ * DQ];
__device__ bf16 g_hh[(size_t)MQ * DQ],  g_hl[(size_t)MQ * DQ];
__device__ bf16 g_y1h[(size_t)EQ * MQ * FFQ], g_y1l[(size_t)EQ * MQ * FFQ];
__device__ bf16 g_fh[(size_t)MQ * DQ],  g_fl[(size_t)MQ * DQ];
__device__ bf16 g_w1h[(size_t)EQ * FFQ * 3 * DQ],  g_w1l[(size_t)EQ * FFQ * 3 * DQ];
__device__ bf16 g_w2h[(size_t)EQ * DQ * 3 * FFQ],  g_w2l[(size_t)EQ * DQ * 3 * FFQ];
__device__ bf16 g_fc1h[DQ * DQ], g_fc1l[DQ * DQ];
__device__ bf16 g_owh[CLSQ * DQ], g_owl[CLSQ * DQ];

__device__ __forceinline__ uint32_t smem_u32(const void* p) {
    uint32_t a;
    asm("{ .reg .u64 t; cvta.to.shared.u64 t, %1; cvt.u32.u64 %0, t; }" : "=r"(a) : "l"(p));
    return a;
}
__device__ __forceinline__ void cp16(uint32_t dst, const void* src, int pred) {
    int sz = pred ? 16 : 0;
    asm volatile("cp.async.cg.shared.global [%0], [%1], 16, %2;"
                 :: "r"(dst), "l"(src), "r"(sz));
}
__device__ __forceinline__ void ldsm4(uint32_t* r, uint32_t addr) {
    asm volatile("ldmatrix.sync.aligned.m8n8.x4.shared.b16 {%0,%1,%2,%3}, [%4];"
                 : "=r"(r[0]), "=r"(r[1]), "=r"(r[2]), "=r"(r[3]) : "r"(addr));
}
__device__ __forceinline__ void mma16816(float* d, const uint32_t* a, const uint32_t* b) {
    asm volatile(
        "mma.sync.aligned.m16n8k16.row.col.f32.bf16.bf16.f32 "
        "{%0,%1,%2,%3}, {%4,%5,%6,%7}, {%8,%9}, {%0,%1,%2,%3};"
        : "+f"(d[0]), "+f"(d[1]), "+f"(d[2]), "+f"(d[3])
        : "r"(a[0]), "r"(a[1]), "r"(a[2]), "r"(a[3]), "r"(b[0]), "r"(b[1]));
}
__device__ __forceinline__ uint32_t pk2(bf16 a, bf16 b) {
    __nv_bfloat162 t = __halves2bfloat162(a, b);
    return *reinterpret_cast<uint32_t*>(&t);
}

// C[m,c] = sum_{k'} A[m+shift(k'), kcol] * W[c,k']   (hi/lo bf16, 3-pass HMMA)
// z = blockIdx.z selects expert: pointer offsets aZ/bZ/biasZ/cZ, idxlist + z*MQ, cnt[z].
// SLOT: idx entries encoded (n<<1)|slot; epilogue writes row slot*MQ+n.
// EPI 0: Cf = acc+bias (guard c<Nrows)
// EPI 1: relu(acc+bias) -> Coh/Col (bf16 hi/lo), rows scattered by idx
// EPI 2: (acc+bias)*gate[n,z] -> Cf at row slot*MQ+n
template<int EPI, int USE_IDX, int SLOT>
__global__ __launch_bounds__(256, 1)
void gemm_hmma(const bf16* __restrict__ Ah, const bf16* __restrict__ Al,
               const bf16* __restrict__ Bh, const bf16* __restrict__ Bl,
               const float* __restrict__ bias,
               float* __restrict__ Cf, bf16* __restrict__ Coh, bf16* __restrict__ Col,
               const float* __restrict__ gates,
               const int* __restrict__ idxlist, const int* __restrict__ cntptr,
               int Nrows, int Kseg, int KW, int strideA,
               size_t aZ, size_t bZ, int biasZ, size_t cZ)
{
    extern __shared__ char smem[];
    __shared__ int srow[GBM];
    __shared__ char sslot[GBM];
    const int tid = threadIdx.x;
    const int lane = tid & 31;
    const int wid = tid >> 5;
    const int wr = wid >> 2;      // 0..1 (m)
    const int wc = wid & 3;       // 0..3 (n)
    const int m0 = blockIdx.y * GBM;
    const int c0 = blockIdx.x * GBN;
    const int z = blockIdx.z;
    const int K = Kseg * KW;
    const int KT = K >> 5;
    const int HALO = KW >> 1;
    const uint32_t sb = smem_u32(smem);

    Ah += (size_t)z * aZ;  Al += (size_t)z * aZ;
    Bh += (size_t)z * bZ;  Bl += (size_t)z * bZ;
    bias += z * biasZ;

    if (USE_IDX) {
        int cnt = cntptr[z];
        if (m0 >= cnt) return;
        if (tid < GBM) {
            int gi = m0 + tid;
            int v = (gi < cnt) ? idxlist[(size_t)z * MQ + gi] : -1;
            if (SLOT) {
                srow[tid] = (v >= 0) ? (v >> 1) : -1;
                sslot[tid] = (v >= 0) ? (v & 1) : 0;
            } else {
                srow[tid] = v;
                sslot[tid] = 0;
            }
        }
        __syncthreads();
    }

    float acc[4][4][4];
    #pragma unroll
    for (int i = 0; i < 4; i++)
        #pragma unroll
        for (int j = 0; j < 4; j++)
            #pragma unroll
            for (int k = 0; k < 4; k++) acc[i][j][k] = 0.f;

    auto load_stage = [&](int stage, int kt) {
        const int k0 = kt * GBK;
        const int kw = k0 / Kseg;
        const int kcol = k0 - kw * Kseg;
        const int dt = kw - HALO;
        const uint32_t ss = sb + stage * STAGE_BYTES;
        #pragma unroll
        for (int i = 0; i < 2; i++) {
            int idx = i * 256 + tid;
            int r = idx >> 2, c = idx & 3;
            int m, valid;
            if (USE_IDX) { m = srow[r]; valid = (m >= 0); }
            else { m = m0 + r; valid = 1; }
            int t = (m & (TQ - 1)) + dt;
            int pr = valid && (t >= 0) && (t < TQ);
            int msafe = pr ? (m + dt) : 0;
            size_t off = (size_t)msafe * strideA + kcol + c * 8;
            uint32_t d = ss + r * 80 + c * 16;
            cp16(d, Ah + off, pr);
            cp16(d + A_LO_OFF, Al + off, pr);
        }
        #pragma unroll
        for (int i = 0; i < 2; i++) {
            int idx = i * 256 + tid;
            int r = idx >> 2, c = idx & 3;
            int n = c0 + r;
            int pr = n < Nrows;
            size_t off = pr ? ((size_t)n * K + k0 + c * 8) : 0;
            uint32_t d = ss + B_HI_OFF + r * 80 + c * 16;
            cp16(d, Bh + off, pr);
            cp16(d + (B_LO_OFF - B_HI_OFF), Bl + off, pr);
        }
        asm volatile("cp.async.commit_group;" ::: "memory");
    };

    load_stage(0, 0);

    const int arow = wr * 64 + (lane & 15);            // + mi*16
    const uint32_t achunk = (lane & 16) ? 16u : 0u;    // + ks*32
    const int brow = wc * 32 + (lane & 7) + ((lane & 16) ? 8 : 0);  // + nb*16
    const uint32_t bchunk = (lane & 8) ? 16u : 0u;

    for (int kt = 0; kt < KT; kt++) {
        const uint32_t cs = sb + (kt & 1) * STAGE_BYTES;
        asm volatile("cp.async.wait_group 0;" ::: "memory");
        __syncthreads();
        if (kt + 1 < KT) load_stage((kt + 1) & 1, kt + 1);

        #pragma unroll
        for (int ks = 0; ks < 2; ks++) {
            uint32_t ah[4][4], al[4][4], bh[4][2], bl[4][2];
            #pragma unroll
            for (int mi = 0; mi < 4; mi++) {
                uint32_t ad = cs + (arow + mi * 16) * 80 + ks * 32 + achunk;
                ldsm4(ah[mi], ad);
                ldsm4(al[mi], ad + A_LO_OFF);
            }
            #pragma unroll
            for (int nb = 0; nb < 2; nb++) {
                uint32_t tmp[4];
                uint32_t bd = cs + B_HI_OFF + (brow + nb * 16) * 80 + ks * 32 + bchunk;
                ldsm4(tmp, bd);
                bh[nb * 2][0] = tmp[0]; bh[nb * 2][1] = tmp[1];
                bh[nb * 2 + 1][0] = tmp[2]; bh[nb * 2 + 1][1] = tmp[3];
                ldsm4(tmp, bd + (B_LO_OFF - B_HI_OFF));
                bl[nb * 2][0] = tmp[0]; bl[nb * 2][1] = tmp[1];
                bl[nb * 2 + 1][0] = tmp[2]; bl[nb * 2 + 1][1] = tmp[3];
            }
            #pragma unroll
            for (int mi = 0; mi < 4; mi++)
                #pragma unroll
                for (int ni = 0; ni < 4; ni++) {
                    mma16816(acc[mi][ni], ah[mi], bh[ni]);
                    mma16816(acc[mi][ni], ah[mi], bl[ni]);
                    mma16816(acc[mi][ni], al[mi], bh[ni]);
                }
        }
        __syncthreads();
    }

    // epilogue: direct register -> gmem
    #pragma unroll
    for (int mi = 0; mi < 4; mi++) {
        int lr0 = wr * 64 + mi * 16 + (lane >> 2);
        int lr1 = lr0 + 8;
        int r0, r1, v0, v1, s0 = 0, s1 = 0;
        if (USE_IDX) {
            r0 = srow[lr0]; r1 = srow[lr1];
            v0 = (r0 >= 0); v1 = (r1 >= 0);
            if (SLOT) { s0 = sslot[lr0]; s1 = sslot[lr1]; }
            if (r0 < 0) r0 = 0;
            if (r1 < 0) r1 = 0;
        } else {
            r0 = m0 + lr0; r1 = m0 + lr1; v0 = 1; v1 = 1;
        }
        float gg0 = 0.f, gg1 = 0.f;
        if (EPI == 2) {
            if (v0) gg0 = gates[r0 * EQ + z];
            if (v1) gg1 = gates[r1 * EQ + z];
        }
        size_t or0 = (EPI == 2) ? ((size_t)(s0 * MQ + r0)) : (size_t)r0;
        size_t or1 = (EPI == 2) ? ((size_t)(s1 * MQ + r1)) : (size_t)r1;
        if (EPI == 1) {
            or0 = (size_t)z * (cZ ? 1 : 0) * 0 + r0;   // cZ applied to pointer below
            or1 = (size_t)r1;
        }
        bf16* CohZ = Coh; bf16* ColZ = Col;
        if (EPI == 1) { CohZ = Coh + (size_t)z * cZ; ColZ = Col + (size_t)z * cZ; }
        #pragma unroll
        for (int ni = 0; ni < 4; ni++) {
            int c = c0 + wc * 32 + ni * 8 + (lane & 3) * 2;
            if (c >= Nrows) continue;
            float2 bv = *reinterpret_cast<const float2*>(bias + c);
            float* a = acc[mi][ni];
            float w0 = a[0] + bv.x, w1 = a[1] + bv.y;
            float w2 = a[2] + bv.x, w3 = a[3] + bv.y;
            if (EPI == 0) {
                if (v0) *reinterpret_cast<float2*>(Cf + or0 * Nrows + c) = make_float2(w0, w1);
                if (v1) *reinterpret_cast<float2*>(Cf + or1 * Nrows + c) = make_float2(w2, w3);
            } else if (EPI == 1) {
                w0 = fmaxf(w0, 0.f); w1 = fmaxf(w1, 0.f);
                w2 = fmaxf(w2, 0.f); w3 = fmaxf(w3, 0.f);
                bf16 h0 = __float2bfloat16(w0), h1 = __float2bfloat16(w1);
                bf16 h2 = __float2bfloat16(w2), h3 = __float2bfloat16(w3);
                bf16 l0 = __float2bfloat16(w0 - __bfloat162float(h0));
                bf16 l1 = __float2bfloat16(w1 - __bfloat162float(h1));
                bf16 l2 = __float2bfloat16(w2 - __bfloat162float(h2));
                bf16 l3 = __float2bfloat16(w3 - __bfloat162float(h3));
                if (v0) {
                    *reinterpret_cast<uint32_t*>(CohZ + or0 * Nrows + c) = pk2(h0, h1);
                    *reinterpret_cast<uint32_t*>(ColZ + or0 * Nrows + c) = pk2(l0, l1);
                }
                if (v1) {
                    *reinterpret_cast<uint32_t*>(CohZ + or1 * Nrows + c) = pk2(h2, h3);
                    *reinterpret_cast<uint32_t*>(ColZ + or1 * Nrows + c) = pk2(l2, l3);
                }
            } else {
                w0 *= gg0; w1 *= gg0; w2 *= gg1; w3 *= gg1;
                if (v0) *reinterpret_cast<float2*>(Cf + or0 * DQ + c) = make_float2(w0, w1);
                if (v1) *reinterpret_cast<float2*>(Cf + or1 * DQ + c) = make_float2(w2, w3);
            }
        }
    }
}

__global__ void split_kernel(const float* __restrict__ src, bf16* __restrict__ h,
                             bf16* __restrict__ l, int n) {
    int i = blockIdx.x * 256 + threadIdx.x;
    if (i < n) {
        float v = src[i];
        bf16 hh = __float2bfloat16(v);
        h[i] = hh;
        l[i] = __float2bfloat16(v - __bfloat162float(hh));
    }
}
// [rows][Kseg][KW] -> [rows][KW][Kseg]
__global__ void perm_kernel(const float* __restrict__ w, bf16* __restrict__ h,
                            bf16* __restrict__ l, int rows, int Kseg) {
    int i = blockIdx.x * 256 + threadIdx.x;
    if (i >= rows * 3 * Kseg) return;
    int row = i / (3 * Kseg);
    int rem = i - row * 3 * Kseg;
    int kw = rem / Kseg, d = rem - kw * Kseg;
    float v = w[(size_t)row * 3 * Kseg + (size_t)d * 3 + kw];
    bf16 hh = __float2bfloat16(v);
    h[i] = hh;
    l[i] = __float2bfloat16(v - __bfloat162float(hh));
}

// per-expert sorted index lists: selected (encoded with slot) and dilated (plain)
__global__ void build_idx() {
    int e = blockIdx.x;
    int tid = threadIdx.x;   // 256
    __shared__ int ss[256], sd[256];
    int base = tid * 32;
    uint32_t selm = 0, dilm = 0, slotm = 0;
    for (int i = 0; i < 32; i++) {
        int n = base + i;
        int t = n & (TQ - 1);
        bool sel = g_gates[n * EQ + e] > 0.f;
        bool dil = sel;
        if (t > 0) dil = dil || (g_gates[(n - 1) * EQ + e] > 0.f);
        if (t < TQ - 1) dil = dil || (g_gates[(n + 1) * EQ + e] > 0.f);
        if (sel) {
            selm |= (1u << i);
            int slot = 0;
            for (int ep = 0; ep < e; ep++)
                if (g_gates[n * EQ + ep] > 0.f) slot++;
            if (slot) slotm |= (1u << i);   // slot is 0 or 1 (exactly 2 selected)
        }
        if (dil) dilm |= (1u << i);
    }
    int cs = __popc(selm), cd = __popc(dilm);
    ss[tid] = cs; sd[tid] = cd;
    __syncthreads();
    for (int o = 1; o < 256; o <<= 1) {
        int vs = (tid >= o) ? ss[tid - o] : 0;
        int vd = (tid >= o) ? sd[tid - o] : 0;
        __syncthreads();
        ss[tid] += vs; sd[tid] += vd;
        __syncthreads();
    }
    int ps = ss[tid] - cs, pd = sd[tid] - cd;
    for (int i = 0; i < 32; i++) {
        int n = base + i;
        if (selm & (1u << i)) {
            int slot = (slotm >> i) & 1;
            g_selidx[e * MQ + ps++] = (n << 1) | slot;
        }
        if (dilm & (1u << i)) g_dilidx[e * MQ + pd++] = n;
    }
    if (tid == 255) { g_selcnt[e] = ss[255]; g_dilcnt[e] = sd[255]; }
}

__device__ __forceinline__ float blockReduceSum256(float v, float* sh) {
    int tid = threadIdx.x;
    #pragma unroll
    for (int o = 16; o > 0; o >>= 1) v += __shfl_down_sync(0xffffffffu, v, o);
    if ((tid & 31) == 0) sh[tid >> 5] = v;
    __syncthreads();
    if (tid < 8) {
        float r = sh[tid];
        #pragma unroll
        for (int o = 4; o > 0; o >>= 1) r += __shfl_down_sync(0xffu, r, o);
        if (tid == 0) sh[0] = r;
    }
    __syncthreads();
    float r = sh[0];
    __syncthreads();
    return r;
}
__device__ __forceinline__ float blockReduceMax256(float v, float* sh) {
    int tid = threadIdx.x;
    #pragma unroll
    for (int o = 16; o > 0; o >>= 1) v = fmaxf(v, __shfl_down_sync(0xffffffffu, v, o));
    if ((tid & 31) == 0) sh[tid >> 5] = v;
    __syncthreads();
    if (tid < 8) {
        float r = sh[tid];
        #pragma unroll
        for (int o = 4; o > 0; o >>= 1) r = fmaxf(r, __shfl_down_sync(0xffu, r, o));
        if (tid == 0) sh[0] = r;
    }
    __syncthreads();
    float r = sh[0];
    __syncthreads();
    return r;
}

__global__ void init_kernel() {
    int i = threadIdx.x;
    for (int d = i; d < DQ; d += 256) { g_sum[d] = 0.f; g_sumsq[d] = 0.f; }
}

__global__ void stats_partial(const int* __restrict__ mask) {
    int d = blockIdx.y * 256 + threadIdx.x;
    int r0 = blockIdx.x * 256;
    float s = 0.f, s2 = 0.f;
    for (int r = 0; r < 256; r++) {
        int n = r0 + r;
        if (mask[n]) {
            float v = g_h[(size_t)n * DQ + d];
            s += v; s2 += v * v;
        }
    }
    atomicAdd(&g_sum[d], s);
    atomicAdd(&g_sumsq[d], s2);
}

__global__ void stats_final(const int* __restrict__ mask,
                            const float* __restrict__ bn_g,
                            const float* __restrict__ bn_b) {
    __shared__ float sh[32];
    __shared__ float s_cnt;
    int tid = threadIdx.x;  // 1024
    float c = 0.f;
    for (int n = tid; n < MQ; n += 1024) c += (float)mask[n];
    #pragma unroll
    for (int o = 16; o > 0; o >>= 1) c += __shfl_down_sync(0xffffffffu, c, o);
    if ((tid & 31) == 0) sh[tid >> 5] = c;
    __syncthreads();
    if (tid < 32) {
        c = sh[tid];
        #pragma unroll
        for (int o = 16; o > 0; o >>= 1) c += __shfl_down_sync(0xffffffffu, c, o);
        if (tid == 0) s_cnt = fmaxf(c, 1.f);
    }
    __syncthreads();
    float cnt = s_cnt;
    int d = tid;
    float mean = g_sum[d] / cnt;
    float var = fmaxf(g_sumsq[d] / cnt - mean * mean, 0.f);
    float sc = rsqrtf(var + 1e-5f) * bn_g[d];
    g_scale[d] = sc;
    g_shift[d] = bn_b[d] - mean * sc;
}

__global__ void norm_gate(const int* __restrict__ mask,
                          const float* __restrict__ pe,
                          const float* __restrict__ gate_w) {
    int n = blockIdx.x;
    int t = n % TQ;
    int m = mask[n];
    int tid = threadIdx.x;
    float g0 = 0.f, g1 = 0.f, g2 = 0.f, g3 = 0.f;
    for (int d = tid; d < DQ; d += 256) {
        float v = g_h[(size_t)n * DQ + d];
        if (m) v = v * g_scale[d] + g_shift[d];
        v = fmaxf(v, 0.f) + pe[t * DQ + d];
        bf16 hh = __float2bfloat16(v);
        g_hh[(size_t)n * DQ + d] = hh;
        g_hl[(size_t)n * DQ + d] = __float2bfloat16(v - __bfloat162float(hh));
        const float4 gw = *reinterpret_cast<const float4*>(gate_w + d * EQ);
        g0 += v * gw.x; g1 += v * gw.y; g2 += v * gw.z; g3 += v * gw.w;
    }
    __shared__ float sh[8][4];
    #pragma unroll
    for (int o = 16; o > 0; o >>= 1) {
        g0 += __shfl_down_sync(0xffffffffu, g0, o);
        g1 += __shfl_down_sync(0xffffffffu, g1, o);
        g2 += __shfl_down_sync(0xffffffffu, g2, o);
        g3 += __shfl_down_sync(0xffffffffu, g3, o);
    }
    if ((tid & 31) == 0) {
        int w = tid >> 5;
        sh[w][0] = g0; sh[w][1] = g1; sh[w][2] = g2; sh[w][3] = g3;
    }
    __syncthreads();
    if (tid == 0) {
        float l[4] = {0.f, 0.f, 0.f, 0.f};
        for (int w = 0; w < 8; w++)
            for (int e = 0; e < 4; e++) l[e] += sh[w][e];
        float mx = fmaxf(fmaxf(l[0], l[1]), fmaxf(l[2], l[3]));
        float ex[4], s = 0.f;
        for (int e = 0; e < 4; e++) { ex[e] = expf(l[e] - mx); s += ex[e]; }
        for (int e = 0; e < 4; e++) g_probs[n * EQ + e] = ex[e] / s;
        int i0 = 0;
        for (int e = 1; e < 4; e++) if (l[e] > l[i0]) i0 = e;
        int i1 = -1;
        for (int e = 0; e < 4; e++) {
            if (e == i0) continue;
            if (i1 < 0 || l[e] > l[i1]) i1 = e;
        }
        float ee = expf(l[i1] - l[i0]);
        float gt[4] = {0.f, 0.f, 0.f, 0.f};
        gt[i0] = 1.f / (1.f + ee);
        gt[i1] = ee / (1.f + ee);
        for (int e = 0; e < 4; e++) g_gates[n * EQ + e] = gt[e];
    }
}

__global__ void ln_kernel(const float* __restrict__ ln_g,
                          const float* __restrict__ ln_b,
                          float* __restrict__ feat,
                          float* __restrict__ featn) {
    __shared__ float sh[8];
    int n = blockIdx.x;
    int tid = threadIdx.x;
    float v[4];
    float s = 0.f;
    #pragma unroll
    for (int i = 0; i < 4; i++) {
        int d = tid + i * 256;
        v[i] = g_moe2[(size_t)n * DQ + d] + g_moe2[(size_t)(MQ + n) * DQ + d];
        s += v[i];
    }
    float mu = blockReduceSum256(s, sh) * (1.f / DQ);
    float q = 0.f;
    #pragma unroll
    for (int i = 0; i < 4; i++) { float dd = v[i] - mu; q += dd * dd; }
    float var = blockReduceSum256(q, sh) * (1.f / DQ);
    float r = rsqrtf(var + 1e-6f);
    float f[4];
    float ss = 0.f;
    #pragma unroll
    for (int i = 0; i < 4; i++) {
        int d = tid + i * 256;
        f[i] = (v[i] - mu) * r * ln_g[d] + ln_b[d];
        feat[(size_t)n * DQ + d] = f[i];
        bf16 hh = __float2bfloat16(f[i]);
        g_fh[(size_t)n * DQ + d] = hh;
        g_fl[(size_t)n * DQ + d] = __float2bfloat16(f[i] - __bfloat162float(hh));
        ss += f[i] * f[i];
    }
    float nrm = fmaxf(sqrtf(blockReduceSum256(ss, sh)), 1e-12f);
    float inv = 1.f / nrm;
    #pragma unroll
    for (int i = 0; i < 4; i++) {
        int d = tid + i * 256;
        featn[(size_t)n * DQ + d] = f[i] * inv;
    }
}

__global__ void softmax_kernel(const float* __restrict__ logits,
                               float* __restrict__ logp,
                               float* __restrict__ p) {
    __shared__ float sh[8];
    int n = blockIdx.x;
    int tid = threadIdx.x;
    const float* row = logits + (size_t)n * CLSQ;
    float mx = -1e30f;
    for (int c = tid; c < CLSQ; c += 256) mx = fmaxf(mx, row[c]);
    mx = blockReduceMax256(mx, sh);
    float s = 0.f;
    for (int c = tid; c < CLSQ; c += 256) s += expf(row[c] - mx);
    s = blockReduceSum256(s, sh);
    float lse = mx + logf(s);
    for (int c = tid; c < CLSQ; c += 256) {
        float lp = row[c] - lse;
        logp[(size_t)n * CLSQ + c] = lp;
        p[(size_t)n * CLSQ + c] = expf(lp);
    }
}

__global__ void aux_kernel(float* __restrict__ out_aux) {
    __shared__ float sh[8];
    int tid = threadIdx.x;
    float imp[4] = {0.f, 0.f, 0.f, 0.f};
    float frc[4] = {0.f, 0.f, 0.f, 0.f};
    for (int n = tid; n < MQ; n += 256) {
        #pragma unroll
        for (int e = 0; e < 4; e++) {
            imp[e] += g_probs[n * EQ + e];
            frc[e] += (g_gates[n * EQ + e] > 0.f) ? 1.f : 0.f;
        }
    }
    float tot[8];
    #pragma unroll
    for (int e = 0; e < 4; e++) tot[e] = blockReduceSum256(imp[e], sh);
    #pragma unroll
    for (int e = 0; e < 4; e++) tot[4 + e] = blockReduceSum256(frc[e], sh);
    if (tid == 0) {
        float aux = 0.f;
        for (int e = 0; e < 4; e++)
            aux += (tot[4 + e] / (float)MQ) * (tot[e] / (float)MQ);
        out_aux[0] = (float)EQ * aux;
    }
}

extern "C" void kernel_launch(void* const* d_in, const int* in_sizes, int n_in,
                              void* d_out, int out_size) {
    const float* x      = (const float*)d_in[0];
    const int*   mask   = (const int*)  d_in[1];
    const float* fc1_w  = (const float*)d_in[2];
    const float* fc1_b  = (const float*)d_in[3];
    const float* bn_g   = (const float*)d_in[4];
    const float* bn_b   = (const float*)d_in[5];
    const float* pe     = (const float*)d_in[6];
    const float* gate_w = (const float*)d_in[7];
    const float* ew1    = (const float*)d_in[8];
    const float* eb1    = (const float*)d_in[9];
    const float* ew2    = (const float*)d_in[10];
    const float* eb2    = (const float*)d_in[11];
    const float* ln_g   = (const float*)d_in[12];
    const float* ln_b   = (const float*)d_in[13];
    const float* out_w  = (const float*)d_in[14];
    const float* out_b  = (const float*)d_in[15];

    float* out = (float*)d_out;
    const size_t FEAT = (size_t)MQ * DQ;
    const size_t LGT  = (size_t)MQ * CLSQ;
    float* feat   = out;
    float* featn  = out + FEAT;
    float* logits = out + 2 * FEAT;
    float* logp   = logits + LGT;
    float* p      = logp + LGT;
    float* aux    = p + LGT;

    float *h, *moe2, *gates;
    bf16 *xh, *xl, *hh, *hl, *y1h, *y1l, *fh, *fl;
    bf16 *w1h, *w1l, *w2h, *w2l, *fc1h, *fc1l, *owh, *owl;
    int *selidx, *dilidx, *selcnt, *dilcnt;
    cudaGetSymbolAddress((void**)&h,     g_h);
    cudaGetSymbolAddress((void**)&moe2,  g_moe2);
    cudaGetSymbolAddress((void**)&gates, g_gates);
    cudaGetSymbolAddress((void**)&xh,  g_xh);   cudaGetSymbolAddress((void**)&xl,  g_xl);
    cudaGetSymbolAddress((void**)&hh,  g_hh);   cudaGetSymbolAddress((void**)&hl,  g_hl);
    cudaGetSymbolAddress((void**)&y1h, g_y1h);  cudaGetSymbolAddress((void**)&y1l, g_y1l);
    cudaGetSymbolAddress((void**)&fh,  g_fh);   cudaGetSymbolAddress((void**)&fl,  g_fl);
    cudaGetSymbolAddress((void**)&w1h, g_w1h);  cudaGetSymbolAddress((void**)&w1l, g_w1l);
    cudaGetSymbolAddress((void**)&w2h, g_w2h);  cudaGetSymbolAddress((void**)&w2l, g_w2l);
    cudaGetSymbolAddress((void**)&fc1h, g_fc1h); cudaGetSymbolAddress((void**)&fc1l, g_fc1l);
    cudaGetSymbolAddress((void**)&owh, g_owh);  cudaGetSymbolAddress((void**)&owl, g_owl);
    cudaGetSymbolAddress((void**)&selidx, g_selidx);
    cudaGetSymbolAddress((void**)&dilidx, g_dilidx);
    cudaGetSymbolAddress((void**)&selcnt, g_selcnt);
    cudaGetSymbolAddress((void**)&dilcnt, g_dilcnt);

    cudaFuncSetAttribute(gemm_hmma<0,0,0>, cudaFuncAttributeMaxDynamicSharedMemorySize, SMEM_GEMM);
    cudaFuncSetAttribute(gemm_hmma<1,1,0>, cudaFuncAttributeMaxDynamicSharedMemorySize, SMEM_GEMM);
    cudaFuncSetAttribute(gemm_hmma<2,1,1>, cudaFuncAttributeMaxDynamicSharedMemorySize, SMEM_GEMM);

    init_kernel<<<1, 256>>>();

    split_kernel<<<(MQ * DQ) / 256, 256>>>(x, xh, xl, MQ * DQ);
    split_kernel<<<(DQ * DQ) / 256, 256>>>(fc1_w, fc1h, fc1l, DQ * DQ);
    split_kernel<<<(CLSQ * DQ) / 256, 256>>>(out_w, owh, owl, CLSQ * DQ);
    perm_kernel<<<(EQ * FFQ * 3 * DQ) / 256, 256>>>(ew1, w1h, w1l, EQ * FFQ, DQ);
    perm_kernel<<<(EQ * DQ * 3 * FFQ) / 256, 256>>>(ew2, w2h, w2l, EQ * DQ, FFQ);

    // fc1: bf16 3-pass dense
    gemm_hmma<0,0,0><<<dim3(DQ / GBN, MQ / GBM), 256, SMEM_GEMM>>>(
        xh, xl, fc1h, fc1l, fc1_b, h, nullptr, nullptr, nullptr,
        nullptr, nullptr, DQ, DQ, 1, DQ, 0, 0, 0, 0);

    stats_partial<<<dim3(32, 4), 256>>>(mask);
    stats_final<<<1, 1024>>>(mask, bn_g, bn_b);
    norm_gate<<<MQ, 256>>>(mask, pe, gate_w);
    build_idx<<<EQ, 256>>>();

    // conv1 fused over experts: dilated token set, y1 per expert (z-strided)
    gemm_hmma<1,1,0><<<dim3(FFQ / GBN, MQ / GBM, EQ), 256, SMEM_GEMM>>>(
        hh, hl, w1h, w1l, eb1, nullptr, y1h, y1l, nullptr,
        dilidx, dilcnt, FFQ, DQ, 3, DQ,
        0, (size_t)FFQ * 3 * DQ, FFQ, (size_t)MQ * FFQ);

    // conv2 fused over experts: selected token set, gate-scaled, slot-buffer writes
    gemm_hmma<2,1,1><<<dim3(DQ / GBN, MQ / GBM, EQ), 256, SMEM_GEMM>>>(
        y1h, y1l, w2h, w2l, eb2, moe2, nullptr, nullptr, gates,
        selidx, selcnt, DQ, FFQ, 3, FFQ,
        (size_t)MQ * FFQ, (size_t)DQ * 3 * FFQ, DQ, 0);

    ln_kernel<<<MQ, 256>>>(ln_g, ln_b, feat, featn);

    gemm_hmma<0,0,0><<<dim3((CLSQ + GBN - 1) / GBN, MQ / GBM), 256, SMEM_GEMM>>>(
        fh, fl, owh, owl, out_b, logits, nullptr, nullptr, nullptr,
        nullptr, nullptr, CLSQ, DQ, 1, DQ, 0, 0, 0, 0);

    softmax_kernel<<<MQ, 256>>>(logits, logp, p);
    aux_kernel<<<1, 256>>>(aux);
}

// round 15
// speedup vs baseline: 1.5151x; 1.0185x over previous
#include <cuda_runtime.h>
#include <cuda_bf16.h>
#include <math.h>
#include <stdint.h>

typedef __nv_bfloat16 bf16;

#define BQ 16
#define TQ 512
#define DQ 1024
#define FFQ 2048
#define EQ 4
#define CLSQ 1200
#define MQ (BQ*TQ)

// GEMM tiling
#define GBM 128
#define GBN 128
#define GBK 32
#define A_LO_OFF 10240
#define B_HI_OFF 20480
#define B_LO_OFF 30720
#define STAGE_BYTES 40960
#define SMEM_GEMM (3*STAGE_BYTES)   // 122880 (3-stage ring)

__device__ float g_h[(size_t)MQ * DQ];
__device__ float g_moe2[(size_t)2 * MQ * DQ];   // slot-major: [slot][token][d]
__device__ float g_gates[MQ * EQ];
__device__ float g_probs[MQ * EQ];
__device__ float g_sum[DQ];
__device__ float g_sumsq[DQ];
__device__ float g_scale[DQ];
__device__ float g_shift[DQ];

__device__ int g_selidx[EQ * MQ];   // encoded (n<<1)|slot
__device__ int g_dilidx[EQ * MQ];   // plain n
__device__ int g_selcnt[EQ];
__device__ int g_dilcnt[EQ];

__device__ bf16 g_xh[(size_t)MQ * DQ],  g_xl[(size_t)MQ * DQ];
__device__ bf16 g_hh[(size_t)MQ * DQ],  g_hl[(size_t)MQ * DQ];
__device__ bf16 g_y1h[(size_t)EQ * MQ * FFQ], g_y1l[(size_t)EQ * MQ * FFQ];
__device__ bf16 g_fh[(size_t)MQ * DQ],  g_fl[(size_t)MQ * DQ];
__device__ bf16 g_w1h[(size_t)EQ * FFQ * 3 * DQ],  g_w1l[(size_t)EQ * FFQ * 3 * DQ];
__device__ bf16 g_w2h[(size_t)EQ * DQ * 3 * FFQ],  g_w2l[(size_t)EQ * DQ * 3 * FFQ];
__device__ bf16 g_fc1h[DQ * DQ], g_fc1l[DQ * DQ];
__device__ bf16 g_owh[CLSQ * DQ], g_owl[CLSQ * DQ];

__device__ __forceinline__ uint32_t smem_u32(const void* p) {
    uint32_t a;
    asm("{ .reg .u64 t; cvta.to.shared.u64 t, %1; cvt.u32.u64 %0, t; }" : "=r"(a) : "l"(p));
    return a;
}
__device__ __forceinline__ void cp16(uint32_t dst, const void* src, int pred) {
    int sz = pred ? 16 : 0;
    asm volatile("cp.async.cg.shared.global [%0], [%1], 16, %2;"
                 :: "r"(dst), "l"(src), "r"(sz));
}
__device__ __forceinline__ void ldsm4(uint32_t* r, uint32_t addr) {
    asm volatile("ldmatrix.sync.aligned.m8n8.x4.shared.b16 {%0,%1,%2,%3}, [%4];"
                 : "=r"(r[0]), "=r"(r[1]), "=r"(r[2]), "=r"(r[3]) : "r"(addr));
}
__device__ __forceinline__ void mma16816(float* d, const uint32_t* a, const uint32_t* b) {
    asm volatile(
        "mma.sync.aligned.m16n8k16.row.col.f32.bf16.bf16.f32 "
        "{%0,%1,%2,%3}, {%4,%5,%6,%7}, {%8,%9}, {%0,%1,%2,%3};"
        : "+f"(d[0]), "+f"(d[1]), "+f"(d[2]), "+f"(d[3])
        : "r"(a[0]), "r"(a[1]), "r"(a[2]), "r"(a[3]), "r"(b[0]), "r"(b[1]));
}
__device__ __forceinline__ uint32_t pk2(bf16 a, bf16 b) {
    __nv_bfloat162 t = __halves2bfloat162(a, b);
    return *reinterpret_cast<uint32_t*>(&t);
}

// C[m,c] = sum_{k'} A[m+shift(k'), kcol] * W[c,k']   (hi/lo bf16, 3-pass HMMA)
// z = blockIdx.z selects expert via pointer offsets aZ/bZ/biasZ/cZ.
template<int EPI, int USE_IDX, int SLOT>
__global__ __launch_bounds__(256, 1)
void gemm_hmma(const bf16* __restrict__ Ah, const bf16* __restrict__ Al,
               const bf16* __restrict__ Bh, const bf16* __restrict__ Bl,
               const float* __restrict__ bias,
               float* __restrict__ Cf, bf16* __restrict__ Coh, bf16* __restrict__ Col,
               const float* __restrict__ gates,
               const int* __restrict__ idxlist, const int* __restrict__ cntptr,
               int Nrows, int Kseg, int KW, int strideA,
               size_t aZ, size_t bZ, int biasZ, size_t cZ)
{
    extern __shared__ char smem[];
    __shared__ int srow[GBM];
    __shared__ char sslot[GBM];
    const int tid = threadIdx.x;
    const int lane = tid & 31;
    const int wid = tid >> 5;
    const int wr = wid >> 2;      // 0..1 (m)
    const int wc = wid & 3;       // 0..3 (n)
    const int m0 = blockIdx.y * GBM;
    const int c0 = blockIdx.x * GBN;
    const int z = blockIdx.z;
    const int K = Kseg * KW;
    const int KT = K >> 5;
    const int HALO = KW >> 1;
    const uint32_t sb = smem_u32(smem);

    Ah += (size_t)z * aZ;  Al += (size_t)z * aZ;
    Bh += (size_t)z * bZ;  Bl += (size_t)z * bZ;
    bias += z * biasZ;

    if (USE_IDX) {
        int cnt = cntptr[z];
        if (m0 >= cnt) return;
        if (tid < GBM) {
            int gi = m0 + tid;
            int v = (gi < cnt) ? idxlist[(size_t)z * MQ + gi] : -1;
            if (SLOT) {
                srow[tid] = (v >= 0) ? (v >> 1) : -1;
                sslot[tid] = (v >= 0) ? (v & 1) : 0;
            } else {
                srow[tid] = v;
                sslot[tid] = 0;
            }
        }
        __syncthreads();
    }

    float acc[4][4][4];
    #pragma unroll
    for (int i = 0; i < 4; i++)
        #pragma unroll
        for (int j = 0; j < 4; j++)
            #pragma unroll
            for (int k = 0; k < 4; k++) acc[i][j][k] = 0.f;

    auto load_stage = [&](int stage, int kt) {
        const int k0 = kt * GBK;
        const int kw = k0 / Kseg;
        const int kcol = k0 - kw * Kseg;
        const int dt = kw - HALO;
        const uint32_t ss = sb + stage * STAGE_BYTES;
        #pragma unroll
        for (int i = 0; i < 2; i++) {
            int idx = i * 256 + tid;
            int r = idx >> 2, c = idx & 3;
            int m, valid;
            if (USE_IDX) { m = srow[r]; valid = (m >= 0); }
            else { m = m0 + r; valid = 1; }
            int t = (m & (TQ - 1)) + dt;
            int pr = valid && (t >= 0) && (t < TQ);
            int msafe = pr ? (m + dt) : 0;
            size_t off = (size_t)msafe * strideA + kcol + c * 8;
            uint32_t d = ss + r * 80 + c * 16;
            cp16(d, Ah + off, pr);
            cp16(d + A_LO_OFF, Al + off, pr);
        }
        #pragma unroll
        for (int i = 0; i < 2; i++) {
            int idx = i * 256 + tid;
            int r = idx >> 2, c = idx & 3;
            int n = c0 + r;
            int pr = n < Nrows;
            size_t off = pr ? ((size_t)n * K + k0 + c * 8) : 0;
            uint32_t d = ss + B_HI_OFF + r * 80 + c * 16;
            cp16(d, Bh + off, pr);
            cp16(d + (B_LO_OFF - B_HI_OFF), Bl + off, pr);
        }
        asm volatile("cp.async.commit_group;" ::: "memory");
    };

    // 3-stage ring prologue
    load_stage(0, 0);
    if (KT > 1) load_stage(1, 1);

    const int arow = wr * 64 + (lane & 15);            // + mi*16
    const uint32_t achunk = (lane & 16) ? 16u : 0u;    // + ks*32
    const int brow = wc * 32 + (lane & 7) + ((lane & 16) ? 8 : 0);  // + nb*16
    const uint32_t bchunk = (lane & 8) ? 16u : 0u;

    int s_cur = 0;
    for (int kt = 0; kt < KT; kt++) {
        if (kt + 1 < KT) asm volatile("cp.async.wait_group 1;" ::: "memory");
        else             asm volatile("cp.async.wait_group 0;" ::: "memory");
        __syncthreads();
        if (kt + 2 < KT) {
            int s_nxt = s_cur + 2; if (s_nxt >= 3) s_nxt -= 3;
            load_stage(s_nxt, kt + 2);
        }
        const uint32_t cs = sb + s_cur * STAGE_BYTES;

        #pragma unroll
        for (int ks = 0; ks < 2; ks++) {
            uint32_t ah[4][4], al[4][4], bh[4][2], bl[4][2];
            #pragma unroll
            for (int mi = 0; mi < 4; mi++) {
                uint32_t ad = cs + (arow + mi * 16) * 80 + ks * 32 + achunk;
                ldsm4(ah[mi], ad);
                ldsm4(al[mi], ad + A_LO_OFF);
            }
            #pragma unroll
            for (int nb = 0; nb < 2; nb++) {
                uint32_t tmp[4];
                uint32_t bd = cs + B_HI_OFF + (brow + nb * 16) * 80 + ks * 32 + bchunk;
                ldsm4(tmp, bd);
                bh[nb * 2][0] = tmp[0]; bh[nb * 2][1] = tmp[1];
                bh[nb * 2 + 1][0] = tmp[2]; bh[nb * 2 + 1][1] = tmp[3];
                ldsm4(tmp, bd + (B_LO_OFF - B_HI_OFF));
                bl[nb * 2][0] = tmp[0]; bl[nb * 2][1] = tmp[1];
                bl[nb * 2 + 1][0] = tmp[2]; bl[nb * 2 + 1][1] = tmp[3];
            }
            #pragma unroll
            for (int mi = 0; mi < 4; mi++)
                #pragma unroll
                for (int ni = 0; ni < 4; ni++) {
                    mma16816(acc[mi][ni], ah[mi], bh[ni]);
                    mma16816(acc[mi][ni], ah[mi], bl[ni]);
                    mma16816(acc[mi][ni], al[mi], bh[ni]);
                }
        }
        s_cur = (s_cur + 1 == 3) ? 0 : s_cur + 1;
    }

    // epilogue: direct register -> gmem
    #pragma unroll
    for (int mi = 0; mi < 4; mi++) {
        int lr0 = wr * 64 + mi * 16 + (lane >> 2);
        int lr1 = lr0 + 8;
        int r0, r1, v0, v1, s0 = 0, s1 = 0;
        if (USE_IDX) {
            r0 = srow[lr0]; r1 = srow[lr1];
            v0 = (r0 >= 0); v1 = (r1 >= 0);
            if (SLOT) { s0 = sslot[lr0]; s1 = sslot[lr1]; }
            if (r0 < 0) r0 = 0;
            if (r1 < 0) r1 = 0;
        } else {
            r0 = m0 + lr0; r1 = m0 + lr1; v0 = 1; v1 = 1;
        }
        float gg0 = 0.f, gg1 = 0.f;
        if (EPI == 2) {
            if (v0) gg0 = gates[r0 * EQ + z];
            if (v1) gg1 = gates[r1 * EQ + z];
        }
        size_t or0 = (size_t)r0, or1 = (size_t)r1;
        if (EPI == 2) { or0 = (size_t)(s0 * MQ + r0); or1 = (size_t)(s1 * MQ + r1); }
        bf16* CohZ = Coh; bf16* ColZ = Col;
        if (EPI == 1) { CohZ = Coh + (size_t)z * cZ; ColZ = Col + (size_t)z * cZ; }
        #pragma unroll
        for (int ni = 0; ni < 4; ni++) {
            int c = c0 + wc * 32 + ni * 8 + (lane & 3) * 2;
            if (c >= Nrows) continue;
            float2 bv = *reinterpret_cast<const float2*>(bias + c);
            float* a = acc[mi][ni];
            float w0 = a[0] + bv.x, w1 = a[1] + bv.y;
            float w2 = a[2] + bv.x, w3 = a[3] + bv.y;
            if (EPI == 0) {
                if (v0) *reinterpret_cast<float2*>(Cf + or0 * Nrows + c) = make_float2(w0, w1);
                if (v1) *reinterpret_cast<float2*>(Cf + or1 * Nrows + c) = make_float2(w2, w3);
            } else if (EPI == 1) {
                w0 = fmaxf(w0, 0.f); w1 = fmaxf(w1, 0.f);
                w2 = fmaxf(w2, 0.f); w3 = fmaxf(w3, 0.f);
                bf16 h0 = __float2bfloat16(w0), h1 = __float2bfloat16(w1);
                bf16 h2 = __float2bfloat16(w2), h3 = __float2bfloat16(w3);
                bf16 l0 = __float2bfloat16(w0 - __bfloat162float(h0));
                bf16 l1 = __float2bfloat16(w1 - __bfloat162float(h1));
                bf16 l2 = __float2bfloat16(w2 - __bfloat162float(h2));
                bf16 l3 = __float2bfloat16(w3 - __bfloat162float(h3));
                if (v0) {
                    *reinterpret_cast<uint32_t*>(CohZ + or0 * Nrows + c) = pk2(h0, h1);
                    *reinterpret_cast<uint32_t*>(ColZ + or0 * Nrows + c) = pk2(l0, l1);
                }
                if (v1) {
                    *reinterpret_cast<uint32_t*>(CohZ + or1 * Nrows + c) = pk2(h2, h3);
                    *reinterpret_cast<uint32_t*>(ColZ + or1 * Nrows + c) = pk2(l2, l3);
                }
            } else {
                w0 *= gg0; w1 *= gg0; w2 *= gg1; w3 *= gg1;
                if (v0) *reinterpret_cast<float2*>(Cf + or0 * Nrows + c) = make_float2(w0, w1);
                if (v1) *reinterpret_cast<float2*>(Cf + or1 * Nrows + c) = make_float2(w2, w3);
            }
        }
    }
}

// vectorized: 8 elems/thread
__global__ void split_kernel(const float* __restrict__ src, bf16* __restrict__ h,
                             bf16* __restrict__ l, int n) {
    int i = (blockIdx.x * 256 + threadIdx.x) * 8;
    if (i >= n) return;
    float4 a = *reinterpret_cast<const float4*>(src + i);
    float4 b = *reinterpret_cast<const float4*>(src + i + 4);
    float va[8] = {a.x, a.y, a.z, a.w, b.x, b.y, b.z, b.w};
    uint32_t hw[4], lw[4];
    #pragma unroll
    for (int j = 0; j < 4; j++) {
        bf16 h0 = __float2bfloat16(va[2*j]), h1 = __float2bfloat16(va[2*j+1]);
        hw[j] = pk2(h0, h1);
        lw[j] = pk2(__float2bfloat16(va[2*j]   - __bfloat162float(h0)),
                    __float2bfloat16(va[2*j+1] - __bfloat162float(h1)));
    }
    *reinterpret_cast<uint4*>(h + i) = make_uint4(hw[0], hw[1], hw[2], hw[3]);
    *reinterpret_cast<uint4*>(l + i) = make_uint4(lw[0], lw[1], lw[2], lw[3]);
}

// [rows][Kseg][KW] -> [rows][KW][Kseg], 4 outputs/thread
__global__ void perm_kernel(const float* __restrict__ w, bf16* __restrict__ h,
                            bf16* __restrict__ l, int rows, int Kseg) {
    int base = (blockIdx.x * 256 + threadIdx.x) * 4;
    if (base >= rows * 3 * Kseg) return;
    int row = base / (3 * Kseg);
    int rem = base - row * 3 * Kseg;
    int kw = rem / Kseg, d = rem - kw * Kseg;
    const float* src = w + (size_t)row * 3 * Kseg + kw;
    uint32_t hw[2], lw[2];
    #pragma unroll
    for (int j = 0; j < 2; j++) {
        float v0 = src[(d + 2*j) * 3];
        float v1 = src[(d + 2*j + 1) * 3];
        bf16 h0 = __float2bfloat16(v0), h1 = __float2bfloat16(v1);
        hw[j] = pk2(h0, h1);
        lw[j] = pk2(__float2bfloat16(v0 - __bfloat162float(h0)),
                    __float2bfloat16(v1 - __bfloat162float(h1)));
    }
    *reinterpret_cast<uint2*>(h + base) = make_uint2(hw[0], hw[1]);
    *reinterpret_cast<uint2*>(l + base) = make_uint2(lw[0], lw[1]);
}

// per-expert sorted index lists: selected (encoded with slot) and dilated (plain)
__global__ void build_idx() {
    int e = blockIdx.x;
    int tid = threadIdx.x;   // 256
    __shared__ int ss[256], sd[256];
    int base = tid * 32;
    uint32_t selm = 0, dilm = 0, slotm = 0;
    for (int i = 0; i < 32; i++) {
        int n = base + i;
        int t = n & (TQ - 1);
        bool sel = g_gates[n * EQ + e] > 0.f;
        bool dil = sel;
        if (t > 0) dil = dil || (g_gates[(n - 1) * EQ + e] > 0.f);
        if (t < TQ - 1) dil = dil || (g_gates[(n + 1) * EQ + e] > 0.f);
        if (sel) {
            selm |= (1u << i);
            int slot = 0;
            for (int ep = 0; ep < e; ep++)
                if (g_gates[n * EQ + ep] > 0.f) slot++;
            if (slot) slotm |= (1u << i);
        }
        if (dil) dilm |= (1u << i);
    }
    int cs = __popc(selm), cd = __popc(dilm);
    ss[tid] = cs; sd[tid] = cd;
    __syncthreads();
    for (int o = 1; o < 256; o <<= 1) {
        int vs = (tid >= o) ? ss[tid - o] : 0;
        int vd = (tid >= o) ? sd[tid - o] : 0;
        __syncthreads();
        ss[tid] += vs; sd[tid] += vd;
        __syncthreads();
    }
    int ps = ss[tid] - cs, pd = sd[tid] - cd;
    for (int i = 0; i < 32; i++) {
        int n = base + i;
        if (selm & (1u << i)) {
            int slot = (slotm >> i) & 1;
            g_selidx[e * MQ + ps++] = (n << 1) | slot;
        }
        if (dilm & (1u << i)) g_dilidx[e * MQ + pd++] = n;
    }
    if (tid == 255) { g_selcnt[e] = ss[255]; g_dilcnt[e] = sd[255]; }
}

__device__ __forceinline__ float blockReduceSum256(float v, float* sh) {
    int tid = threadIdx.x;
    #pragma unroll
    for (int o = 16; o > 0; o >>= 1) v += __shfl_down_sync(0xffffffffu, v, o);
    if ((tid & 31) == 0) sh[tid >> 5] = v;
    __syncthreads();
    if (tid < 8) {
        float r = sh[tid];
        #pragma unroll
        for (int o = 4; o > 0; o >>= 1) r += __shfl_down_sync(0xffu, r, o);
        if (tid == 0) sh[0] = r;
    }
    __syncthreads();
    float r = sh[0];
    __syncthreads();
    return r;
}
__device__ __forceinline__ float blockReduceMax256(float v, float* sh) {
    int tid = threadIdx.x;
    #pragma unroll
    for (int o = 16; o > 0; o >>= 1) v = fmaxf(v, __shfl_down_sync(0xffffffffu, v, o));
    if ((tid & 31) == 0) sh[tid >> 5] = v;
    __syncthreads();
    if (tid < 8) {
        float r = sh[tid];
        #pragma unroll
        for (int o = 4; o > 0; o >>= 1) r = fmaxf(r, __shfl_down_sync(0xffu, r, o));
        if (tid == 0) sh[0] = r;
    }
    __syncthreads();
    float r = sh[0];
    __syncthreads();
    return r;
}

__global__ void init_kernel() {
    int i = threadIdx.x;
    for (int d = i; d < DQ; d += 256) { g_sum[d] = 0.f; g_sumsq[d] = 0.f; }
}

__global__ void stats_partial(const int* __restrict__ mask) {
    __shared__ float smask[256];
    int d = blockIdx.y * 256 + threadIdx.x;
    int r0 = blockIdx.x * 256;
    smask[threadIdx.x] = (float)mask[r0 + threadIdx.x];
    __syncthreads();
    float s = 0.f, s2 = 0.f;
    #pragma unroll 4
    for (int r = 0; r < 256; r++) {
        float v = g_h[(size_t)(r0 + r) * DQ + d];
        float mf = smask[r];
        s += v * mf;
        s2 += v * v * mf;
    }
    atomicAdd(&g_sum[d], s);
    atomicAdd(&g_sumsq[d], s2);
}

__global__ void stats_final(const int* __restrict__ mask,
                            const float* __restrict__ bn_g,
                            const float* __restrict__ bn_b) {
    __shared__ float sh[32];
    __shared__ float s_cnt;
    int tid = threadIdx.x;  // 1024
    float c = 0.f;
    for (int n = tid; n < MQ; n += 1024) c += (float)mask[n];
    #pragma unroll
    for (int o = 16; o > 0; o >>= 1) c += __shfl_down_sync(0xffffffffu, c, o);
    if ((tid & 31) == 0) sh[tid >> 5] = c;
    __syncthreads();
    if (tid < 32) {
        c = sh[tid];
        #pragma unroll
        for (int o = 16; o > 0; o >>= 1) c += __shfl_down_sync(0xffffffffu, c, o);
        if (tid == 0) s_cnt = fmaxf(c, 1.f);
    }
    __syncthreads();
    float cnt = s_cnt;
    int d = tid;
    float mean = g_sum[d] / cnt;
    float var = fmaxf(g_sumsq[d] / cnt - mean * mean, 0.f);
    float sc = rsqrtf(var + 1e-5f) * bn_g[d];
    g_scale[d] = sc;
    g_shift[d] = bn_b[d] - mean * sc;
}

__global__ void norm_gate(const int* __restrict__ mask,
                          const float* __restrict__ pe,
                          const float* __restrict__ gate_w) {
    int n = blockIdx.x;
    int t = n % TQ;
    int m = mask[n];
    int tid = threadIdx.x;
    int d = tid * 4;     // DQ = 256*4, single pass
    float4 hv = *reinterpret_cast<const float4*>(g_h + (size_t)n * DQ + d);
    if (m) {
        float4 sc = *reinterpret_cast<const float4*>(g_scale + d);
        float4 sf = *reinterpret_cast<const float4*>(g_shift + d);
        hv.x = hv.x * sc.x + sf.x; hv.y = hv.y * sc.y + sf.y;
        hv.z = hv.z * sc.z + sf.z; hv.w = hv.w * sc.w + sf.w;
    }
    float4 pv = *reinterpret_cast<const float4*>(pe + (size_t)t * DQ + d);
    float va[4];
    va[0] = fmaxf(hv.x, 0.f) + pv.x;
    va[1] = fmaxf(hv.y, 0.f) + pv.y;
    va[2] = fmaxf(hv.z, 0.f) + pv.z;
    va[3] = fmaxf(hv.w, 0.f) + pv.w;
    uint32_t hw[2], lw[2];
    #pragma unroll
    for (int j = 0; j < 2; j++) {
        bf16 h0 = __float2bfloat16(va[2*j]), h1 = __float2bfloat16(va[2*j+1]);
        hw[j] = pk2(h0, h1);
        lw[j] = pk2(__float2bfloat16(va[2*j]   - __bfloat162float(h0)),
                    __float2bfloat16(va[2*j+1] - __bfloat162float(h1)));
    }
    *reinterpret_cast<uint2*>(g_hh + (size_t)n * DQ + d) = make_uint2(hw[0], hw[1]);
    *reinterpret_cast<uint2*>(g_hl + (size_t)n * DQ + d) = make_uint2(lw[0], lw[1]);

    float g0 = 0.f, g1 = 0.f, g2 = 0.f, g3 = 0.f;
    #pragma unroll
    for (int j = 0; j < 4; j++) {
        const float4 gw = *reinterpret_cast<const float4*>(gate_w + (d + j) * EQ);
        g0 += va[j] * gw.x; g1 += va[j] * gw.y; g2 += va[j] * gw.z; g3 += va[j] * gw.w;
    }
    __shared__ float sh[8][4];
    #pragma unroll
    for (int o = 16; o > 0; o >>= 1) {
        g0 += __shfl_down_sync(0xffffffffu, g0, o);
        g1 += __shfl_down_sync(0xffffffffu, g1, o);
        g2 += __shfl_down_sync(0xffffffffu, g2, o);
        g3 += __shfl_down_sync(0xffffffffu, g3, o);
    }
    if ((tid & 31) == 0) {
        int w = tid >> 5;
        sh[w][0] = g0; sh[w][1] = g1; sh[w][2] = g2; sh[w][3] = g3;
    }
    __syncthreads();
    if (tid == 0) {
        float l[4] = {0.f, 0.f, 0.f, 0.f};
        for (int w = 0; w < 8; w++)
            for (int e = 0; e < 4; e++) l[e] += sh[w][e];
        float mx = fmaxf(fmaxf(l[0], l[1]), fmaxf(l[2], l[3]));
        float ex[4], s = 0.f;
        for (int e = 0; e < 4; e++) { ex[e] = expf(l[e] - mx); s += ex[e]; }
        for (int e = 0; e < 4; e++) g_probs[n * EQ + e] = ex[e] / s;
        int i0 = 0;
        for (int e = 1; e < 4; e++) if (l[e] > l[i0]) i0 = e;
        int i1 = -1;
        for (int e = 0; e < 4; e++) {
            if (e == i0) continue;
            if (i1 < 0 || l[e] > l[i1]) i1 = e;
        }
        float ee = expf(l[i1] - l[i0]);
        float gt[4] = {0.f, 0.f, 0.f, 0.f};
        gt[i0] = 1.f / (1.f + ee);
        gt[i1] = ee / (1.f + ee);
        for (int e = 0; e < 4; e++) g_gates[n * EQ + e] = gt[e];
    }
}

__global__ void ln_kernel(const float* __restrict__ ln_g,
                          const float* __restrict__ ln_b,
                          float* __restrict__ feat,
                          float* __restrict__ featn) {
    __shared__ float sh[8];
    int n = blockIdx.x;
    int tid = threadIdx.x;
    int d = tid * 4;
    float4 a = *reinterpret_cast<const float4*>(g_moe2 + (size_t)n * DQ + d);
    float4 b = *reinterpret_cast<const float4*>(g_moe2 + (size_t)(MQ + n) * DQ + d);
    float v[4] = {a.x + b.x, a.y + b.y, a.z + b.z, a.w + b.w};
    float s = v[0] + v[1] + v[2] + v[3];
    float mu = blockReduceSum256(s, sh) * (1.f / DQ);
    float q = 0.f;
    #pragma unroll
    for (int i = 0; i < 4; i++) { float dd = v[i] - mu; q += dd * dd; }
    float var = blockReduceSum256(q, sh) * (1.f / DQ);
    float r = rsqrtf(var + 1e-6f);
    float4 lg = *reinterpret_cast<const float4*>(ln_g + d);
    float4 lb = *reinterpret_cast<const float4*>(ln_b + d);
    float f[4];
    f[0] = (v[0] - mu) * r * lg.x + lb.x;
    f[1] = (v[1] - mu) * r * lg.y + lb.y;
    f[2] = (v[2] - mu) * r * lg.z + lb.z;
    f[3] = (v[3] - mu) * r * lg.w + lb.w;
    *reinterpret_cast<float4*>(feat + (size_t)n * DQ + d) = make_float4(f[0], f[1], f[2], f[3]);
    uint32_t hw[2], lw[2];
    #pragma unroll
    for (int j = 0; j < 2; j++) {
        bf16 h0 = __float2bfloat16(f[2*j]), h1 = __float2bfloat16(f[2*j+1]);
        hw[j] = pk2(h0, h1);
        lw[j] = pk2(__float2bfloat16(f[2*j]   - __bfloat162float(h0)),
                    __float2bfloat16(f[2*j+1] - __bfloat162float(h1)));
    }
    *reinterpret_cast<uint2*>(g_fh + (size_t)n * DQ + d) = make_uint2(hw[0], hw[1]);
    *reinterpret_cast<uint2*>(g_fl + (size_t)n * DQ + d) = make_uint2(lw[0], lw[1]);
    float ss = f[0]*f[0] + f[1]*f[1] + f[2]*f[2] + f[3]*f[3];
    float nrm = fmaxf(sqrtf(blockReduceSum256(ss, sh)), 1e-12f);
    float inv = 1.f / nrm;
    *reinterpret_cast<float4*>(featn + (size_t)n * DQ + d) =
        make_float4(f[0]*inv, f[1]*inv, f[2]*inv, f[3]*inv);
}

__global__ void softmax_kernel(const float* __restrict__ logits,
                               float* __restrict__ logp,
                               float* __restrict__ p) {
    __shared__ float sh[8];
    int n = blockIdx.x;
    int tid = threadIdx.x;
    const float4* row4 = reinterpret_cast<const float4*>(logits + (size_t)n * CLSQ);
    const int C4 = CLSQ / 4;   // 300
    float mx = -1e30f;
    for (int c = tid; c < C4; c += 256) {
        float4 v = row4[c];
        mx = fmaxf(mx, fmaxf(fmaxf(v.x, v.y), fmaxf(v.z, v.w)));
    }
    mx = blockReduceMax256(mx, sh);
    float s = 0.f;
    for (int c = tid; c < C4; c += 256) {
        float4 v = row4[c];
        s += expf(v.x - mx) + expf(v.y - mx) + expf(v.z - mx) + expf(v.w - mx);
    }
    s = blockReduceSum256(s, sh);
    float lse = mx + logf(s);
    float4* lp4 = reinterpret_cast<float4*>(logp + (size_t)n * CLSQ);
    float4* p4  = reinterpret_cast<float4*>(p + (size_t)n * CLSQ);
    for (int c = tid; c < C4; c += 256) {
        float4 v = row4[c];
        float4 o;
        o.x = v.x - lse; o.y = v.y - lse; o.z = v.z - lse; o.w = v.w - lse;
        lp4[c] = o;
        p4[c] = make_float4(expf(o.x), expf(o.y), expf(o.z), expf(o.w));
    }
}

__global__ void aux_kernel(float* __restrict__ out_aux) {
    __shared__ float sh[8];
    int tid = threadIdx.x;
    float imp[4] = {0.f, 0.f, 0.f, 0.f};
    float frc[4] = {0.f, 0.f, 0.f, 0.f};
    for (int n = tid; n < MQ; n += 256) {
        #pragma unroll
        for (int e = 0; e < 4; e++) {
            imp[e] += g_probs[n * EQ + e];
            frc[e] += (g_gates[n * EQ + e] > 0.f) ? 1.f : 0.f;
        }
    }
    float tot[8];
    #pragma unroll
    for (int e = 0; e < 4; e++) tot[e] = blockReduceSum256(imp[e], sh);
    #pragma unroll
    for (int e = 0; e < 4; e++) tot[4 + e] = blockReduceSum256(frc[e], sh);
    if (tid == 0) {
        float aux = 0.f;
        for (int e = 0; e < 4; e++)
            aux += (tot[4 + e] / (float)MQ) * (tot[e] / (float)MQ);
        out_aux[0] = (float)EQ * aux;
    }
}

extern "C" void kernel_launch(void* const* d_in, const int* in_sizes, int n_in,
                              void* d_out, int out_size) {
    const float* x      = (const float*)d_in[0];
    const int*   mask   = (const int*)  d_in[1];
    const float* fc1_w  = (const float*)d_in[2];
    const float* fc1_b  = (const float*)d_in[3];
    const float* bn_g   = (const float*)d_in[4];
    const float* bn_b   = (const float*)d_in[5];
    const float* pe     = (const float*)d_in[6];
    const float* gate_w = (const float*)d_in[7];
    const float* ew1    = (const float*)d_in[8];
    const float* eb1    = (const float*)d_in[9];
    const float* ew2    = (const float*)d_in[10];
    const float* eb2    = (const float*)d_in[11];
    const float* ln_g   = (const float*)d_in[12];
    const float* ln_b   = (const float*)d_in[13];
    const float* out_w  = (const float*)d_in[14];
    const float* out_b  = (const float*)d_in[15];

    float* out = (float*)d_out;
    const size_t FEAT = (size_t)MQ * DQ;
    const size_t LGT  = (size_t)MQ * CLSQ;
    float* feat   = out;
    float* featn  = out + FEAT;
    float* logits = out + 2 * FEAT;
    float* logp   = logits + LGT;
    float* p      = logp + LGT;
    float* aux    = p + LGT;

    float *h, *moe2, *gates;
    bf16 *xh, *xl, *hh, *hl, *y1h, *y1l, *fh, *fl;
    bf16 *w1h, *w1l, *w2h, *w2l, *fc1h, *fc1l, *owh, *owl;
    int *selidx, *dilidx, *selcnt, *dilcnt;
    cudaGetSymbolAddress((void**)&h,     g_h);
    cudaGetSymbolAddress((void**)&moe2,  g_moe2);
    cudaGetSymbolAddress((void**)&gates, g_gates);
    cudaGetSymbolAddress((void**)&xh,  g_xh);   cudaGetSymbolAddress((void**)&xl,  g_xl);
    cudaGetSymbolAddress((void**)&hh,  g_hh);   cudaGetSymbolAddress((void**)&hl,  g_hl);
    cudaGetSymbolAddress((void**)&y1h, g_y1h);  cudaGetSymbolAddress((void**)&y1l, g_y1l);
    cudaGetSymbolAddress((void**)&fh,  g_fh);   cudaGetSymbolAddress((void**)&fl,  g_fl);
    cudaGetSymbolAddress((void**)&w1h, g_w1h);  cudaGetSymbolAddress((void**)&w1l, g_w1l);
    cudaGetSymbolAddress((void**)&w2h, g_w2h);  cudaGetSymbolAddress((void**)&w2l, g_w2l);
    cudaGetSymbolAddress((void**)&fc1h, g_fc1h); cudaGetSymbolAddress((void**)&fc1l, g_fc1l);
    cudaGetSymbolAddress((void**)&owh, g_owh);  cudaGetSymbolAddress((void**)&owl, g_owl);
    cudaGetSymbolAddress((void**)&selidx, g_selidx);
    cudaGetSymbolAddress((void**)&dilidx, g_dilidx);
    cudaGetSymbolAddress((void**)&selcnt, g_selcnt);
    cudaGetSymbolAddress((void**)&dilcnt, g_dilcnt);

    cudaFuncSetAttribute(gemm_hmma<0,0,0>, cudaFuncAttributeMaxDynamicSharedMemorySize, SMEM_GEMM);
    cudaFuncSetAttribute(gemm_hmma<1,1,0>, cudaFuncAttributeMaxDynamicSharedMemorySize, SMEM_GEMM);
    cudaFuncSetAttribute(gemm_hmma<2,1,1>, cudaFuncAttributeMaxDynamicSharedMemorySize, SMEM_GEMM);

    init_kernel<<<1, 256>>>();

    split_kernel<<<(MQ * DQ) / 2048, 256>>>(x, xh, xl, MQ * DQ);
    split_kernel<<<(DQ * DQ) / 2048, 256>>>(fc1_w, fc1h, fc1l, DQ * DQ);
    split_kernel<<<(CLSQ * DQ) / 2048, 256>>>(out_w, owh, owl, CLSQ * DQ);
    perm_kernel<<<(EQ * FFQ * 3 * DQ) / 1024, 256>>>(ew1, w1h, w1l, EQ * FFQ, DQ);
    perm_kernel<<<(EQ * DQ * 3 * FFQ) / 1024, 256>>>(ew2, w2h, w2l, EQ * DQ, FFQ);

    // fc1: bf16 3-pass dense
    gemm_hmma<0,0,0><<<dim3(DQ / GBN, MQ / GBM), 256, SMEM_GEMM>>>(
        xh, xl, fc1h, fc1l, fc1_b, h, nullptr, nullptr, nullptr,
        nullptr, nullptr, DQ, DQ, 1, DQ, 0, 0, 0, 0);

    stats_partial<<<dim3(32, 4), 256>>>(mask);
    stats_final<<<1, 1024>>>(mask, bn_g, bn_b);
    norm_gate<<<MQ, 256>>>(mask, pe, gate_w);
    build_idx<<<EQ, 256>>>();

    // conv1 fused over experts: dilated token set, y1 per expert (z-strided)
    gemm_hmma<1,1,0><<<dim3(FFQ / GBN, MQ / GBM, EQ), 256, SMEM_GEMM>>>(
        hh, hl, w1h, w1l, eb1, nullptr, y1h, y1l, nullptr,
        dilidx, dilcnt, FFQ, DQ, 3, DQ,
        0, (size_t)FFQ * 3 * DQ, FFQ, (size_t)MQ * FFQ);

    // conv2 fused over experts: selected token set, gate-scaled, slot-buffer writes
    gemm_hmma<2,1,1><<<dim3(DQ / GBN, MQ / GBM, EQ), 256, SMEM_GEMM>>>(
        y1h, y1l, w2h, w2l, eb2, moe2, nullptr, nullptr, gates,
        selidx, selcnt, DQ, FFQ, 3, FFQ,
        (size_t)MQ * FFQ, (size_t)DQ * 3 * FFQ, DQ, 0);

    ln_kernel<<<MQ, 256>>>(ln_g, ln_b, feat, featn);

    gemm_hmma<0,0,0><<<dim3((CLSQ + GBN - 1) / GBN, MQ / GBM), 256, SMEM_GEMM>>>(
        fh, fl, owh, owl, out_b, logits, nullptr, nullptr, nullptr,
        nullptr, nullptr, CLSQ, DQ, 1, DQ, 0, 0, 0, 0);

    softmax_kernel<<<MQ, 256>>>(logits, logp, p);
    aux_kernel<<<1, 256>>>(aux);
}

// round 17
// speedup vs baseline: 1.8304x; 1.2082x over previous
#include <cuda_runtime.h>
#include <cuda_bf16.h>
#include <math.h>
#include <stdint.h>

typedef __nv_bfloat16 bf16;

#define BQ 16
#define TQ 512
#define DQ 1024
#define FFQ 2048
#define EQ 4
#define CLSQ 1200
#define MQ (BQ*TQ)

// GEMM tiling
#define GBM 128
#define GBN 128
#define GBK 32
#define A_LO_OFF 10240
#define B_HI_OFF 20480
#define B_LO_OFF 30720
#define STAGE_BYTES 40960
#define SMEM_GEMM (2*STAGE_BYTES)   // 81920 -> 2 CTAs/SM

__device__ float g_h[(size_t)MQ * DQ];
__device__ float g_moe2[(size_t)2 * MQ * DQ];   // slot-major: [slot][token][d]
__device__ float g_gates[MQ * EQ];
__device__ float g_probs[MQ * EQ];
__device__ float g_sum[DQ];
__device__ float g_sumsq[DQ];
__device__ float g_scale[DQ];
__device__ float g_shift[DQ];

__device__ int g_selidx[EQ * MQ];   // encoded (n<<1)|slot
__device__ int g_dilidx[EQ * MQ];   // plain n
__device__ int g_selcnt[EQ];
__device__ int g_dilcnt[EQ];

__device__ bf16 g_xh[(size_t)MQ * DQ],  g_xl[(size_t)MQ * DQ];
__device__ bf16 g_hh[(size_t)MQ * DQ],  g_hl[(size_t)MQ * DQ];
__device__ bf16 g_y1h[(size_t)EQ * MQ * FFQ], g_y1l[(size_t)EQ * MQ * FFQ];
__device__ bf16 g_fh[(size_t)MQ * DQ],  g_fl[(size_t)MQ * DQ];
__device__ bf16 g_w1h[(size_t)EQ * FFQ * 3 * DQ],  g_w1l[(size_t)EQ * FFQ * 3 * DQ];
__device__ bf16 g_w2h[(size_t)EQ * DQ * 3 * FFQ],  g_w2l[(size_t)EQ * DQ * 3 * FFQ];
__device__ bf16 g_fc1h[DQ * DQ], g_fc1l[DQ * DQ];
__device__ bf16 g_owh[CLSQ * DQ], g_owl[CLSQ * DQ];

__device__ __forceinline__ uint32_t smem_u32(const void* p) {
    uint32_t a;
    asm("{ .reg .u64 t; cvta.to.shared.u64 t, %1; cvt.u32.u64 %0, t; }" : "=r"(a) : "l"(p));
    return a;
}
__device__ __forceinline__ void cp16(uint32_t dst, const void* src, int pred) {
    int sz = pred ? 16 : 0;
    asm volatile("cp.async.cg.shared.global [%0], [%1], 16, %2;"
                 :: "r"(dst), "l"(src), "r"(sz));
}
__device__ __forceinline__ void ldsm4(uint32_t* r, uint32_t addr) {
    asm volatile("ldmatrix.sync.aligned.m8n8.x4.shared.b16 {%0,%1,%2,%3}, [%4];"
                 : "=r"(r[0]), "=r"(r[1]), "=r"(r[2]), "=r"(r[3]) : "r"(addr));
}
__device__ __forceinline__ void mma16816(float* d, const uint32_t* a, const uint32_t* b) {
    asm volatile(
        "mma.sync.aligned.m16n8k16.row.col.f32.bf16.bf16.f32 "
        "{%0,%1,%2,%3}, {%4,%5,%6,%7}, {%8,%9}, {%0,%1,%2,%3};"
        : "+f"(d[0]), "+f"(d[1]), "+f"(d[2]), "+f"(d[3])
        : "r"(a[0]), "r"(a[1]), "r"(a[2]), "r"(a[3]), "r"(b[0]), "r"(b[1]));
}
__device__ __forceinline__ uint32_t pk2(bf16 a, bf16 b) {
    __nv_bfloat162 t = __halves2bfloat162(a, b);
    return *reinterpret_cast<uint32_t*>(&t);
}

// C[m,c] = sum_{k'} A[m+shift(k'), kcol] * W[c,k']   (hi/lo bf16, 3-pass HMMA)
// z = blockIdx.z selects expert via pointer offsets aZ/bZ/biasZ/cZ.
template<int EPI, int USE_IDX, int SLOT>
__global__ __launch_bounds__(256, 2)
void gemm_hmma(const bf16* __restrict__ Ah, const bf16* __restrict__ Al,
               const bf16* __restrict__ Bh, const bf16* __restrict__ Bl,
               const float* __restrict__ bias,
               float* __restrict__ Cf, bf16* __restrict__ Coh, bf16* __restrict__ Col,
               const float* __restrict__ gates,
               const int* __restrict__ idxlist, const int* __restrict__ cntptr,
               int Nrows, int Kseg, int KW, int strideA,
               size_t aZ, size_t bZ, int biasZ, size_t cZ)
{
    extern __shared__ char smem[];
    __shared__ int srow[GBM];
    __shared__ char sslot[GBM];
    const int tid = threadIdx.x;
    const int lane = tid & 31;
    const int wid = tid >> 5;
    const int wr = wid >> 2;      // 0..1 (m)
    const int wc = wid & 3;       // 0..3 (n)
    const int m0 = blockIdx.y * GBM;
    const int c0 = blockIdx.x * GBN;
    const int z = blockIdx.z;
    const int K = Kseg * KW;
    const int KT = K >> 5;
    const int HALO = KW >> 1;
    const uint32_t sb = smem_u32(smem);

    Ah += (size_t)z * aZ;  Al += (size_t)z * aZ;
    Bh += (size_t)z * bZ;  Bl += (size_t)z * bZ;
    bias += z * biasZ;

    if (USE_IDX) {
        int cnt = cntptr[z];
        if (m0 >= cnt) return;
        if (tid < GBM) {
            int gi = m0 + tid;
            int v = (gi < cnt) ? idxlist[(size_t)z * MQ + gi] : -1;
            if (SLOT) {
                srow[tid] = (v >= 0) ? (v >> 1) : -1;
                sslot[tid] = (v >= 0) ? (v & 1) : 0;
            } else {
                srow[tid] = v;
                sslot[tid] = 0;
            }
        }
        __syncthreads();
    }

    float acc[4][4][4];
    #pragma unroll
    for (int i = 0; i < 4; i++)
        #pragma unroll
        for (int j = 0; j < 4; j++)
            #pragma unroll
            for (int k = 0; k < 4; k++) acc[i][j][k] = 0.f;

    auto load_stage = [&](int stage, int kt) {
        const int k0 = kt * GBK;
        const int kw = k0 / Kseg;
        const int kcol = k0 - kw * Kseg;
        const int dt = kw - HALO;
        const uint32_t ss = sb + stage * STAGE_BYTES;
        #pragma unroll
        for (int i = 0; i < 2; i++) {
            int idx = i * 256 + tid;
            int r = idx >> 2, c = idx & 3;
            int m, valid;
            if (USE_IDX) { m = srow[r]; valid = (m >= 0); }
            else { m = m0 + r; valid = 1; }
            int t = (m & (TQ - 1)) + dt;
            int pr = valid && (t >= 0) && (t < TQ);
            int msafe = pr ? (m + dt) : 0;
            size_t off = (size_t)msafe * strideA + kcol + c * 8;
            uint32_t d = ss + r * 80 + c * 16;
            cp16(d, Ah + off, pr);
            cp16(d + A_LO_OFF, Al + off, pr);
        }
        #pragma unroll
        for (int i = 0; i < 2; i++) {
            int idx = i * 256 + tid;
            int r = idx >> 2, c = idx & 3;
            int n = c0 + r;
            int pr = n < Nrows;
            size_t off = pr ? ((size_t)n * K + k0 + c * 8) : 0;
            uint32_t d = ss + B_HI_OFF + r * 80 + c * 16;
            cp16(d, Bh + off, pr);
            cp16(d + (B_LO_OFF - B_HI_OFF), Bl + off, pr);
        }
        asm volatile("cp.async.commit_group;" ::: "memory");
    };

    load_stage(0, 0);

    const int arow = wr * 64 + (lane & 15);            // + mi*16
    const uint32_t achunk = (lane & 16) ? 16u : 0u;    // + ks*32
    const int brow = wc * 32 + (lane & 7) + ((lane & 16) ? 8 : 0);  // + nb*16
    const uint32_t bchunk = (lane & 8) ? 16u : 0u;

    for (int kt = 0; kt < KT; kt++) {
        const uint32_t cs = sb + (kt & 1) * STAGE_BYTES;
        asm volatile("cp.async.wait_group 0;" ::: "memory");
        __syncthreads();
        if (kt + 1 < KT) load_stage((kt + 1) & 1, kt + 1);

        #pragma unroll
        for (int ks = 0; ks < 2; ks++) {
            uint32_t bh[4][2], bl[4][2];
            #pragma unroll
            for (int nb = 0; nb < 2; nb++) {
                uint32_t tmp[4];
                uint32_t bd = cs + B_HI_OFF + (brow + nb * 16) * 80 + ks * 32 + bchunk;
                ldsm4(tmp, bd);
                bh[nb * 2][0] = tmp[0]; bh[nb * 2][1] = tmp[1];
                bh[nb * 2 + 1][0] = tmp[2]; bh[nb * 2 + 1][1] = tmp[3];
                ldsm4(tmp, bd + (B_LO_OFF - B_HI_OFF));
                bl[nb * 2][0] = tmp[0]; bl[nb * 2][1] = tmp[1];
                bl[nb * 2 + 1][0] = tmp[2]; bl[nb * 2 + 1][1] = tmp[3];
            }
            #pragma unroll
            for (int mi = 0; mi < 4; mi++) {
                uint32_t ah[4], al[4];
                uint32_t ad = cs + (arow + mi * 16) * 80 + ks * 32 + achunk;
                ldsm4(ah, ad);
                ldsm4(al, ad + A_LO_OFF);
                #pragma unroll
                for (int ni = 0; ni < 4; ni++) {
                    mma16816(acc[mi][ni], ah, bh[ni]);
                    mma16816(acc[mi][ni], ah, bl[ni]);
                    mma16816(acc[mi][ni], al, bh[ni]);
                }
            }
        }
        __syncthreads();
    }

    // epilogue: direct register -> gmem
    #pragma unroll
    for (int mi = 0; mi < 4; mi++) {
        int lr0 = wr * 64 + mi * 16 + (lane >> 2);
        int lr1 = lr0 + 8;
        int r0, r1, v0, v1, s0 = 0, s1 = 0;
        if (USE_IDX) {
            r0 = srow[lr0]; r1 = srow[lr1];
            v0 = (r0 >= 0); v1 = (r1 >= 0);
            if (SLOT) { s0 = sslot[lr0]; s1 = sslot[lr1]; }
            if (r0 < 0) r0 = 0;
            if (r1 < 0) r1 = 0;
        } else {
            r0 = m0 + lr0; r1 = m0 + lr1; v0 = 1; v1 = 1;
        }
        float gg0 = 0.f, gg1 = 0.f;
        if (EPI == 2) {
            if (v0) gg0 = gates[r0 * EQ + z];
            if (v1) gg1 = gates[r1 * EQ + z];
        }
        size_t or0 = (size_t)r0, or1 = (size_t)r1;
        if (EPI == 2) { or0 = (size_t)(s0 * MQ + r0); or1 = (size_t)(s1 * MQ + r1); }
        bf16* CohZ = Coh; bf16* ColZ = Col;
        if (EPI == 1) { CohZ = Coh + (size_t)z * cZ; ColZ = Col + (size_t)z * cZ; }
        #pragma unroll
        for (int ni = 0; ni < 4; ni++) {
            int c = c0 + wc * 32 + ni * 8 + (lane & 3) * 2;
            if (c >= Nrows) continue;
            float2 bv = *reinterpret_cast<const float2*>(bias + c);
            float* a = acc[mi][ni];
            float w0 = a[0] + bv.x, w1 = a[1] + bv.y;
            float w2 = a[2] + bv.x, w3 = a[3] + bv.y;
            if (EPI == 0) {
                if (v0) *reinterpret_cast<float2*>(Cf + or0 * Nrows + c) = make_float2(w0, w1);
                if (v1) *reinterpret_cast<float2*>(Cf + or1 * Nrows + c) = make_float2(w2, w3);
            } else if (EPI == 1) {
                w0 = fmaxf(w0, 0.f); w1 = fmaxf(w1, 0.f);
                w2 = fmaxf(w2, 0.f); w3 = fmaxf(w3, 0.f);
                bf16 h0 = __float2bfloat16(w0), h1 = __float2bfloat16(w1);
                bf16 h2 = __float2bfloat16(w2), h3 = __float2bfloat16(w3);
                bf16 l0 = __float2bfloat16(w0 - __bfloat162float(h0));
                bf16 l1 = __float2bfloat16(w1 - __bfloat162float(h1));
                bf16 l2 = __float2bfloat16(w2 - __bfloat162float(h2));
                bf16 l3 = __float2bfloat16(w3 - __bfloat162float(h3));
                if (v0) {
                    *reinterpret_cast<uint32_t*>(CohZ + or0 * Nrows + c) = pk2(h0, h1);
                    *reinterpret_cast<uint32_t*>(ColZ + or0 * Nrows + c) = pk2(l0, l1);
                }
                if (v1) {
                    *reinterpret_cast<uint32_t*>(CohZ + or1 * Nrows + c) = pk2(h2, h3);
                    *reinterpret_cast<uint32_t*>(ColZ + or1 * Nrows + c) = pk2(l2, l3);
                }
            } else {
                w0 *= gg0; w1 *= gg0; w2 *= gg1; w3 *= gg1;
                if (v0) *reinterpret_cast<float2*>(Cf + or0 * Nrows + c) = make_float2(w0, w1);
                if (v1) *reinterpret_cast<float2*>(Cf + or1 * Nrows + c) = make_float2(w2, w3);
            }
        }
    }
}

// vectorized: 8 elems/thread
__global__ void split_kernel(const float* __restrict__ src, bf16* __restrict__ h,
                             bf16* __restrict__ l, int n) {
    int i = (blockIdx.x * 256 + threadIdx.x) * 8;
    if (i >= n) return;
    float4 a = *reinterpret_cast<const float4*>(src + i);
    float4 b = *reinterpret_cast<const float4*>(src + i + 4);
    float va[8] = {a.x, a.y, a.z, a.w, b.x, b.y, b.z, b.w};
    uint32_t hw[4], lw[4];
    #pragma unroll
    for (int j = 0; j < 4; j++) {
        bf16 h0 = __float2bfloat16(va[2*j]), h1 = __float2bfloat16(va[2*j+1]);
        hw[j] = pk2(h0, h1);
        lw[j] = pk2(__float2bfloat16(va[2*j]   - __bfloat162float(h0)),
                    __float2bfloat16(va[2*j+1] - __bfloat162float(h1)));
    }
    *reinterpret_cast<uint4*>(h + i) = make_uint4(hw[0], hw[1], hw[2], hw[3]);
    *reinterpret_cast<uint4*>(l + i) = make_uint4(lw[0], lw[1], lw[2], lw[3]);
}

// [rows][Kseg][KW] -> [rows][KW][Kseg], 4 outputs/thread
__global__ void perm_kernel(const float* __restrict__ w, bf16* __restrict__ h,
                            bf16* __restrict__ l, int rows, int Kseg) {
    int base = (blockIdx.x * 256 + threadIdx.x) * 4;
    if (base >= rows * 3 * Kseg) return;
    int row = base / (3 * Kseg);
    int rem = base - row * 3 * Kseg;
    int kw = rem / Kseg, d = rem - kw * Kseg;
    const float* src = w + (size_t)row * 3 * Kseg + kw;
    uint32_t hw[2], lw[2];
    #pragma unroll
    for (int j = 0; j < 2; j++) {
        float v0 = src[(d + 2*j) * 3];
        float v1 = src[(d + 2*j + 1) * 3];
        bf16 h0 = __float2bfloat16(v0), h1 = __float2bfloat16(v1);
        hw[j] = pk2(h0, h1);
        lw[j] = pk2(__float2bfloat16(v0 - __bfloat162float(h0)),
                    __float2bfloat16(v1 - __bfloat162float(h1)));
    }
    *reinterpret_cast<uint2*>(h + base) = make_uint2(hw[0], hw[1]);
    *reinterpret_cast<uint2*>(l + base) = make_uint2(lw[0], lw[1]);
}

// per-expert sorted index lists: selected (encoded with slot) and dilated (plain)
__global__ void build_idx() {
    int e = blockIdx.x;
    int tid = threadIdx.x;   // 256
    __shared__ int ss[256], sd[256];
    int base = tid * 32;
    uint32_t selm = 0, dilm = 0, slotm = 0;
    for (int i = 0; i < 32; i++) {
        int n = base + i;
        int t = n & (TQ - 1);
        bool sel = g_gates[n * EQ + e] > 0.f;
        bool dil = sel;
        if (t > 0) dil = dil || (g_gates[(n - 1) * EQ + e] > 0.f);
        if (t < TQ - 1) dil = dil || (g_gates[(n + 1) * EQ + e] > 0.f);
        if (sel) {
            selm |= (1u << i);
            int slot = 0;
            for (int ep = 0; ep < e; ep++)
                if (g_gates[n * EQ + ep] > 0.f) slot++;
            if (slot) slotm |= (1u << i);
        }
        if (dil) dilm |= (1u << i);
    }
    int cs = __popc(selm), cd = __popc(dilm);
    ss[tid] = cs; sd[tid] = cd;
    __syncthreads();
    for (int o = 1; o < 256; o <<= 1) {
        int vs = (tid >= o) ? ss[tid - o] : 0;
        int vd = (tid >= o) ? sd[tid - o] : 0;
        __syncthreads();
        ss[tid] += vs; sd[tid] += vd;
        __syncthreads();
    }
    int ps = ss[tid] - cs, pd = sd[tid] - cd;
    for (int i = 0; i < 32; i++) {
        int n = base + i;
        if (selm & (1u << i)) {
            int slot = (slotm >> i) & 1;
            g_selidx[e * MQ + ps++] = (n << 1) | slot;
        }
        if (dilm & (1u << i)) g_dilidx[e * MQ + pd++] = n;
    }
    if (tid == 255) { g_selcnt[e] = ss[255]; g_dilcnt[e] = sd[255]; }
}

__device__ __forceinline__ float blockReduceSum256(float v, float* sh) {
    int tid = threadIdx.x;
    #pragma unroll
    for (int o = 16; o > 0; o >>= 1) v += __shfl_down_sync(0xffffffffu, v, o);
    if ((tid & 31) == 0) sh[tid >> 5] = v;
    __syncthreads();
    if (tid < 8) {
        float r = sh[tid];
        #pragma unroll
        for (int o = 4; o > 0; o >>= 1) r += __shfl_down_sync(0xffu, r, o);
        if (tid == 0) sh[0] = r;
    }
    __syncthreads();
    float r = sh[0];
    __syncthreads();
    return r;
}
__device__ __forceinline__ float blockReduceMax256(float v, float* sh) {
    int tid = threadIdx.x;
    #pragma unroll
    for (int o = 16; o > 0; o >>= 1) v = fmaxf(v, __shfl_down_sync(0xffffffffu, v, o));
    if ((tid & 31) == 0) sh[tid >> 5] = v;
    __syncthreads();
    if (tid < 8) {
        float r = sh[tid];
        #pragma unroll
        for (int o = 4; o > 0; o >>= 1) r = fmaxf(r, __shfl_down_sync(0xffu, r, o));
        if (tid == 0) sh[0] = r;
    }
    __syncthreads();
    float r = sh[0];
    __syncthreads();
    return r;
}

__global__ void init_kernel() {
    int i = threadIdx.x;
    for (int d = i; d < DQ; d += 256) { g_sum[d] = 0.f; g_sumsq[d] = 0.f; }
}

__global__ void stats_partial(const int* __restrict__ mask) {
    __shared__ float smask[256];
    int d = blockIdx.y * 256 + threadIdx.x;
    int r0 = blockIdx.x * 256;
    smask[threadIdx.x] = (float)mask[r0 + threadIdx.x];
    __syncthreads();
    float s = 0.f, s2 = 0.f;
    #pragma unroll 4
    for (int r = 0; r < 256; r++) {
        float v = g_h[(size_t)(r0 + r) * DQ + d];
        float mf = smask[r];
        s += v * mf;
        s2 += v * v * mf;
    }
    atomicAdd(&g_sum[d], s);
    atomicAdd(&g_sumsq[d], s2);
}

__global__ void stats_final(const int* __restrict__ mask,
                            const float* __restrict__ bn_g,
                            const float* __restrict__ bn_b) {
    __shared__ float sh[32];
    __shared__ float s_cnt;
    int tid = threadIdx.x;  // 1024
    float c = 0.f;
    for (int n = tid; n < MQ; n += 1024) c += (float)mask[n];
    #pragma unroll
    for (int o = 16; o > 0; o >>= 1) c += __shfl_down_sync(0xffffffffu, c, o);
    if ((tid & 31) == 0) sh[tid >> 5] = c;
    __syncthreads();
    if (tid < 32) {
        c = sh[tid];
        #pragma unroll
        for (int o = 16; o > 0; o >>= 1) c += __shfl_down_sync(0xffffffffu, c, o);
        if (tid == 0) s_cnt = fmaxf(c, 1.f);
    }
    __syncthreads();
    float cnt = s_cnt;
    int d = tid;
    float mean = g_sum[d] / cnt;
    float var = fmaxf(g_sumsq[d] / cnt - mean * mean, 0.f);
    float sc = rsqrtf(var + 1e-5f) * bn_g[d];
    g_scale[d] = sc;
    g_shift[d] = bn_b[d] - mean * sc;
}

__global__ void norm_gate(const int* __restrict__ mask,
                          const float* __restrict__ pe,
                          const float* __restrict__ gate_w) {
    int n = blockIdx.x;
    int t = n % TQ;
    int m = mask[n];
    int tid = threadIdx.x;
    int d = tid * 4;     // DQ = 256*4, single pass
    float4 hv = *reinterpret_cast<const float4*>(g_h + (size_t)n * DQ + d);
    if (m) {
        float4 sc = *reinterpret_cast<const float4*>(g_scale + d);
        float4 sf = *reinterpret_cast<const float4*>(g_shift + d);
        hv.x = hv.x * sc.x + sf.x; hv.y = hv.y * sc.y + sf.y;
        hv.z = hv.z * sc.z + sf.z; hv.w = hv.w * sc.w + sf.w;
    }
    float4 pv = *reinterpret_cast<const float4*>(pe + (size_t)t * DQ + d);
    float va[4];
    va[0] = fmaxf(hv.x, 0.f) + pv.x;
    va[1] = fmaxf(hv.y, 0.f) + pv.y;
    va[2] = fmaxf(hv.z, 0.f) + pv.z;
    va[3] = fmaxf(hv.w, 0.f) + pv.w;
    uint32_t hw[2], lw[2];
    #pragma unroll
    for (int j = 0; j < 2; j++) {
        bf16 h0 = __float2bfloat16(va[2*j]), h1 = __float2bfloat16(va[2*j+1]);
        hw[j] = pk2(h0, h1);
        lw[j] = pk2(__float2bfloat16(va[2*j]   - __bfloat162float(h0)),
                    __float2bfloat16(va[2*j+1] - __bfloat162float(h1)));
    }
    *reinterpret_cast<uint2*>(g_hh + (size_t)n * DQ + d) = make_uint2(hw[0], hw[1]);
    *reinterpret_cast<uint2*>(g_hl + (size_t)n * DQ + d) = make_uint2(lw[0], lw[1]);

    float g0 = 0.f, g1 = 0.f, g2 = 0.f, g3 = 0.f;
    #pragma unroll
    for (int j = 0; j < 4; j++) {
        const float4 gw = *reinterpret_cast<const float4*>(gate_w + (d + j) * EQ);
        g0 += va[j] * gw.x; g1 += va[j] * gw.y; g2 += va[j] * gw.z; g3 += va[j] * gw.w;
    }
    __shared__ float sh[8][4];
    #pragma unroll
    for (int o = 16; o > 0; o >>= 1) {
        g0 += __shfl_down_sync(0xffffffffu, g0, o);
        g1 += __shfl_down_sync(0xffffffffu, g1, o);
        g2 += __shfl_down_sync(0xffffffffu, g2, o);
        g3 += __shfl_down_sync(0xffffffffu, g3, o);
    }
    if ((tid & 31) == 0) {
        int w = tid >> 5;
        sh[w][0] = g0; sh[w][1] = g1; sh[w][2] = g2; sh[w][3] = g3;
    }
    __syncthreads();
    if (tid == 0) {
        float l[4] = {0.f, 0.f, 0.f, 0.f};
        for (int w = 0; w < 8; w++)
            for (int e = 0; e < 4; e++) l[e] += sh[w][e];
        float mx = fmaxf(fmaxf(l[0], l[1]), fmaxf(l[2], l[3]));
        float ex[4], s = 0.f;
        for (int e = 0; e < 4; e++) { ex[e] = expf(l[e] - mx); s += ex[e]; }
        for (int e = 0; e < 4; e++) g_probs[n * EQ + e] = ex[e] / s;
        int i0 = 0;
        for (int e = 1; e < 4; e++) if (l[e] > l[i0]) i0 = e;
        int i1 = -1;
        for (int e = 0; e < 4; e++) {
            if (e == i0) continue;
            if (i1 < 0 || l[e] > l[i1]) i1 = e;
        }
        float ee = expf(l[i1] - l[i0]);
        float gt[4] = {0.f, 0.f, 0.f, 0.f};
        gt[i0] = 1.f / (1.f + ee);
        gt[i1] = ee / (1.f + ee);
        for (int e = 0; e < 4; e++) g_gates[n * EQ + e] = gt[e];
    }
}

__global__ void ln_kernel(const float* __restrict__ ln_g,
                          const float* __restrict__ ln_b,
                          float* __restrict__ feat,
                          float* __restrict__ featn) {
    __shared__ float sh[8];
    int n = blockIdx.x;
    int tid = threadIdx.x;
    int d = tid * 4;
    float4 a = *reinterpret_cast<const float4*>(g_moe2 + (size_t)n * DQ + d);
    float4 b = *reinterpret_cast<const float4*>(g_moe2 + (size_t)(MQ + n) * DQ + d);
    float v[4] = {a.x + b.x, a.y + b.y, a.z + b.z, a.w + b.w};
    float s = v[0] + v[1] + v[2] + v[3];
    float mu = blockReduceSum256(s, sh) * (1.f / DQ);
    float q = 0.f;
    #pragma unroll
    for (int i = 0; i < 4; i++) { float dd = v[i] - mu; q += dd * dd; }
    float var = blockReduceSum256(q, sh) * (1.f / DQ);
    float r = rsqrtf(var + 1e-6f);
    float4 lg = *reinterpret_cast<const float4*>(ln_g + d);
    float4 lb = *reinterpret_cast<const float4*>(ln_b + d);
    float f[4];
    f[0] = (v[0] - mu) * r * lg.x + lb.x;
    f[1] = (v[1] - mu) * r * lg.y + lb.y;
    f[2] = (v[2] - mu) * r * lg.z + lb.z;
    f[3] = (v[3] - mu) * r * lg.w + lb.w;
    *reinterpret_cast<float4*>(feat + (size_t)n * DQ + d) = make_float4(f[0], f[1], f[2], f[3]);
    uint32_t hw[2], lw[2];
    #pragma unroll
    for (int j = 0; j < 2; j++) {
        bf16 h0 = __float2bfloat16(f[2*j]), h1 = __float2bfloat16(f[2*j+1]);
        hw[j] = pk2(h0, h1);
        lw[j] = pk2(__float2bfloat16(f[2*j]   - __bfloat162float(h0)),
                    __float2bfloat16(f[2*j+1] - __bfloat162float(h1)));
    }
    *reinterpret_cast<uint2*>(g_fh + (size_t)n * DQ + d) = make_uint2(hw[0], hw[1]);
    *reinterpret_cast<uint2*>(g_fl + (size_t)n * DQ + d) = make_uint2(lw[0], lw[1]);
    float ss = f[0]*f[0] + f[1]*f[1] + f[2]*f[2] + f[3]*f[3];
    float nrm = fmaxf(sqrtf(blockReduceSum256(ss, sh)), 1e-12f);
    float inv = 1.f / nrm;
    *reinterpret_cast<float4*>(featn + (size_t)n * DQ + d) =
        make_float4(f[0]*inv, f[1]*inv, f[2]*inv, f[3]*inv);
}

__global__ void softmax_kernel(const float* __restrict__ logits,
                               float* __restrict__ logp,
                               float* __restrict__ p) {
    __shared__ float sh[8];
    int n = blockIdx.x;
    int tid = threadIdx.x;
    const float4* row4 = reinterpret_cast<const float4*>(logits + (size_t)n * CLSQ);
    const int C4 = CLSQ / 4;   // 300
    float mx = -1e30f;
    for (int c = tid; c < C4; c += 256) {
        float4 v = row4[c];
        mx = fmaxf(mx, fmaxf(fmaxf(v.x, v.y), fmaxf(v.z, v.w)));
    }
    mx = blockReduceMax256(mx, sh);
    float s = 0.f;
    for (int c = tid; c < C4; c += 256) {
        float4 v = row4[c];
        s += expf(v.x - mx) + expf(v.y - mx) + expf(v.z - mx) + expf(v.w - mx);
    }
    s = blockReduceSum256(s, sh);
    float lse = mx + logf(s);
    float4* lp4 = reinterpret_cast<float4*>(logp + (size_t)n * CLSQ);
    float4* p4  = reinterpret_cast<float4*>(p + (size_t)n * CLSQ);
    for (int c = tid; c < C4; c += 256) {
        float4 v = row4[c];
        float4 o;
        o.x = v.x - lse; o.y = v.y - lse; o.z = v.z - lse; o.w = v.w - lse;
        lp4[c] = o;
        p4[c] = make_float4(expf(o.x), expf(o.y), expf(o.z), expf(o.w));
    }
}

__global__ void aux_kernel(float* __restrict__ out_aux) {
    __shared__ float sh[8];
    int tid = threadIdx.x;
    float imp[4] = {0.f, 0.f, 0.f, 0.f};
    float frc[4] = {0.f, 0.f, 0.f, 0.f};
    for (int n = tid; n < MQ; n += 256) {
        #pragma unroll
        for (int e = 0; e < 4; e++) {
            imp[e] += g_probs[n * EQ + e];
            frc[e] += (g_gates[n * EQ + e] > 0.f) ? 1.f : 0.f;
        }
    }
    float tot[8];
    #pragma unroll
    for (int e = 0; e < 4; e++) tot[e] = blockReduceSum256(imp[e], sh);
    #pragma unroll
    for (int e = 0; e < 4; e++) tot[4 + e] = blockReduceSum256(frc[e], sh);
    if (tid == 0) {
        float aux = 0.f;
        for (int e = 0; e < 4; e++)
            aux += (tot[4 + e] / (float)MQ) * (tot[e] / (float)MQ);
        out_aux[0] = (float)EQ * aux;
    }
}

extern "C" void kernel_launch(void* const* d_in, const int* in_sizes, int n_in,
                              void* d_out, int out_size) {
    const float* x      = (const float*)d_in[0];
    const int*   mask   = (const int*)  d_in[1];
    const float* fc1_w  = (const float*)d_in[2];
    const float* fc1_b  = (const float*)d_in[3];
    const float* bn_g   = (const float*)d_in[4];
    const float* bn_b   = (const float*)d_in[5];
    const float* pe     = (const float*)d_in[6];
    const float* gate_w = (const float*)d_in[7];
    const float* ew1    = (const float*)d_in[8];
    const float* eb1    = (const float*)d_in[9];
    const float* ew2    = (const float*)d_in[10];
    const float* eb2    = (const float*)d_in[11];
    const float* ln_g   = (const float*)d_in[12];
    const float* ln_b   = (const float*)d_in[13];
    const float* out_w  = (const float*)d_in[14];
    const float* out_b  = (const float*)d_in[15];

    float* out = (float*)d_out;
    const size_t FEAT = (size_t)MQ * DQ;
    const size_t LGT  = (size_t)MQ * CLSQ;
    float* feat   = out;
    float* featn  = out + FEAT;
    float* logits = out + 2 * FEAT;
    float* logp   = logits + LGT;
    float* p      = logp + LGT;
    float* aux    = p + LGT;

    float *h, *moe2, *gates;
    bf16 *xh, *xl, *hh, *hl, *y1h, *y1l, *fh, *fl;
    bf16 *w1h, *w1l, *w2h, *w2l, *fc1h, *fc1l, *owh, *owl;
    int *selidx, *dilidx, *selcnt, *dilcnt;
    cudaGetSymbolAddress((void**)&h,     g_h);
    cudaGetSymbolAddress((void**)&moe2,  g_moe2);
    cudaGetSymbolAddress((void**)&gates, g_gates);
    cudaGetSymbolAddress((void**)&xh,  g_xh);   cudaGetSymbolAddress((void**)&xl,  g_xl);
    cudaGetSymbolAddress((void**)&hh,  g_hh);   cudaGetSymbolAddress((void**)&hl,  g_hl);
    cudaGetSymbolAddress((void**)&y1h, g_y1h);  cudaGetSymbolAddress((void**)&y1l, g_y1l);
    cudaGetSymbolAddress((void**)&fh,  g_fh);   cudaGetSymbolAddress((void**)&fl,  g_fl);
    cudaGetSymbolAddress((void**)&w1h, g_w1h);  cudaGetSymbolAddress((void**)&w1l, g_w1l);
    cudaGetSymbolAddress((void**)&w2h, g_w2h);  cudaGetSymbolAddress((void**)&w2l, g_w2l);
    cudaGetSymbolAddress((void**)&fc1h, g_fc1h); cudaGetSymbolAddress((void**)&fc1l, g_fc1l);
    cudaGetSymbolAddress((void**)&owh, g_owh);  cudaGetSymbolAddress((void**)&owl, g_owl);
    cudaGetSymbolAddress((void**)&selidx, g_selidx);
    cudaGetSymbolAddress((void**)&dilidx, g_dilidx);
    cudaGetSymbolAddress((void**)&selcnt, g_selcnt);
    cudaGetSymbolAddress((void**)&dilcnt, g_dilcnt);

    cudaFuncSetAttribute(gemm_hmma<0,0,0>, cudaFuncAttributeMaxDynamicSharedMemorySize, SMEM_GEMM);
    cudaFuncSetAttribute(gemm_hmma<1,1,0>, cudaFuncAttributeMaxDynamicSharedMemorySize, SMEM_GEMM);
    cudaFuncSetAttribute(gemm_hmma<2,1,1>, cudaFuncAttributeMaxDynamicSharedMemorySize, SMEM_GEMM);

    init_kernel<<<1, 256>>>();

    split_kernel<<<(MQ * DQ) / 2048, 256>>>(x, xh, xl, MQ * DQ);
    split_kernel<<<(DQ * DQ) / 2048, 256>>>(fc1_w, fc1h, fc1l, DQ * DQ);
    split_kernel<<<(CLSQ * DQ) / 2048, 256>>>(out_w, owh, owl, CLSQ * DQ);
    perm_kernel<<<(EQ * FFQ * 3 * DQ) / 1024, 256>>>(ew1, w1h, w1l, EQ * FFQ, DQ);
    perm_kernel<<<(EQ * DQ * 3 * FFQ) / 1024, 256>>>(ew2, w2h, w2l, EQ * DQ, FFQ);

    // fc1: bf16 3-pass dense
    gemm_hmma<0,0,0><<<dim3(DQ / GBN, MQ / GBM), 256, SMEM_GEMM>>>(
        xh, xl, fc1h, fc1l, fc1_b, h, nullptr, nullptr, nullptr,
        nullptr, nullptr, DQ, DQ, 1, DQ, 0, 0, 0, 0);

    stats_partial<<<dim3(32, 4), 256>>>(mask);
    stats_final<<<1, 1024>>>(mask, bn_g, bn_b);
    norm_gate<<<MQ, 256>>>(mask, pe, gate_w);
    build_idx<<<EQ, 256>>>();

    // conv1 fused over experts: dilated token set, y1 per expert (z-strided)
    gemm_hmma<1,1,0><<<dim3(FFQ / GBN, MQ / GBM, EQ), 256, SMEM_GEMM>>>(
        hh, hl, w1h, w1l, eb1, nullptr, y1h, y1l, nullptr,
        dilidx, dilcnt, FFQ, DQ, 3, DQ,
        0, (size_t)FFQ * 3 * DQ, FFQ, (size_t)MQ * FFQ);

    // conv2 fused over experts: selected token set, gate-scaled, slot-buffer writes
    gemm_hmma<2,1,1><<<dim3(DQ / GBN, MQ / GBM, EQ), 256, SMEM_GEMM>>>(
        y1h, y1l, w2h, w2l, eb2, moe2, nullptr, nullptr, gates,
        selidx, selcnt, DQ, FFQ, 3, FFQ,
        (size_t)MQ * FFQ, (size_t)DQ * 3 * FFQ, DQ, 0);

    ln_kernel<<<MQ, 256>>>(ln_g, ln_b, feat, featn);

    gemm_hmma<0,0,0><<<dim3((CLSQ + GBN - 1) / GBN, MQ / GBM), 256, SMEM_GEMM>>>(
        fh, fl, owh, owl, out_b, logits, nullptr, nullptr, nullptr,
        nullptr, nullptr, CLSQ, DQ, 1, DQ, 0, 0, 0, 0);

    softmax_kernel<<<MQ, 256>>>(logits, logp, p);
    aux_kernel<<<1, 256>>>(aux);
}